// round 4
// baseline (speedup 1.0000x reference)
#include <cuda_runtime.h>
#include <math.h>

// Problem constants
constexpr int NN  = 50000;   // nodes
constexpr int DIN = 128;     // input feature dim
constexpr int HO  = 256;     // H*O
constexpr int NH  = 8;       // heads
constexpr int NE  = 400000;  // edges per path
constexpr int NP  = 3;       // metapaths
constexpr int HID = 128;     // semantic hidden

// ---------------- scratch (static device globals; no allocation) ----------------
__device__ float g_h  [(size_t)NP * NN * HO];   // per-path projected features
__device__ float g_out[(size_t)NP * NN * HO];   // per-path GAT output (normalized, pre-bias)
__device__ float g_el [NP * NN * NH];
__device__ float g_er [NP * NN * NH];
__device__ int   g_cnt[NP * NN];                // in-degree per dst
__device__ int   g_off[NP * NN];                // CSR exclusive offsets
__device__ int   g_cur[NP * NN];                // scatter cursors
__device__ int   g_csr[(size_t)NP * NE];        // src node per CSR slot
__device__ float g_wsum[NP];
__device__ float g_beta[NP];
__device__ int   g_is64;

// ---------------- helpers ----------------
__device__ __forceinline__ float elu_f(float x) { return x > 0.f ? x : expm1f(x); }

__device__ __forceinline__ float tanh_fast(float x) {
    float y;
    asm("tanh.approx.f32 %0, %1;" : "=f"(y) : "f"(x));
    return y;
}

// edges may be int64 (jax x64) or int32 (x64 disabled) — uniform device branch
__device__ __forceinline__ int edge_val(const void* edges, size_t idx) {
    if (g_is64) return (int)(((const long long*)edges)[idx]);
    return ((const int*)edges)[idx];
}

// ---------------- kernels ----------------
__global__ void detect_kernel(const int* e32) {
    if (threadIdx.x == 0 && blockIdx.x == 0) {
        int is64 = 1;
        #pragma unroll
        for (int k = 0; k < 16; k++)
            if (e32[2 * k + 1] != 0) is64 = 0;
        g_is64 = is64;
    }
}

// zero counters / cursors / wsum (g_out is fully written by agg_fused)
__global__ void init_small() {
    int i = blockIdx.x * blockDim.x + threadIdx.x;
    if (i < NP * NN) {
        g_cnt[i] = 0;
        g_cur[i] = 0;
    }
    if (i < NP) g_wsum[i] = 0.f;
}

// h_p = feat @ W_p ; BM=64, BN=256(full), BK=16, thread tile 8x8, 256 thr
// Epilogue computes el/er (per node, per head) from register-resident acc.
__global__ void __launch_bounds__(256) gemm_h(const float* __restrict__ feat,
                                              const float* __restrict__ Ws,
                                              const float* __restrict__ al,
                                              const float* __restrict__ ar) {
    int p = blockIdx.y;
    int row0 = blockIdx.x * 64;
    const float* W = Ws + (size_t)p * DIN * HO;
    __shared__ float As[16][65];
    __shared__ float Bs[16][256];
    int tid = threadIdx.x;
    int tcol = tid & 31, trow = tid >> 5;

    float acc[8][8];
    #pragma unroll
    for (int i = 0; i < 8; i++)
        #pragma unroll
        for (int j = 0; j < 8; j++) acc[i][j] = 0.f;

    for (int k0 = 0; k0 < DIN; k0 += 16) {
        #pragma unroll
        for (int it = 0; it < 4; it++) {
            int l = tid + it * 256;
            int r = l >> 4, kk = l & 15;
            int gr = row0 + r;
            As[kk][r] = (gr < NN) ? feat[(size_t)gr * DIN + k0 + kk] : 0.f;
        }
        #pragma unroll
        for (int it = 0; it < 16; it++)
            Bs[it][tid] = W[(size_t)(k0 + it) * HO + tid];
        __syncthreads();
        #pragma unroll
        for (int kk = 0; kk < 16; kk++) {
            float a[8], b[8];
            #pragma unroll
            for (int i = 0; i < 8; i++) a[i] = As[kk][trow * 8 + i];
            #pragma unroll
            for (int j = 0; j < 8; j++) b[j] = Bs[kk][tcol + 32 * j];
            #pragma unroll
            for (int i = 0; i < 8; i++)
                #pragma unroll
                for (int j = 0; j < 8; j++) acc[i][j] += a[i] * b[j];
        }
        __syncthreads();
    }

    // attn vectors: column tcol+32*j lives in head j, o = tcol
    float al_r[8], ar_r[8];
    #pragma unroll
    for (int j = 0; j < 8; j++) {
        al_r[j] = al[p * HO + j * 32 + tcol];
        ar_r[j] = ar[p * HO + j * 32 + tcol];
    }

    #pragma unroll
    for (int i = 0; i < 8; i++) {
        int gr = row0 + trow * 8 + i;
        bool ok = (gr < NN);
        // store h row
        if (ok) {
            float* hrow = g_h + ((size_t)p * NN + gr) * HO;
            #pragma unroll
            for (int j = 0; j < 8; j++) hrow[tcol + 32 * j] = acc[i][j];
        }
        // el/er lane reduction (sum over o = lane dim)
        float pl[8], pr[8];
        #pragma unroll
        for (int j = 0; j < 8; j++) {
            pl[j] = acc[i][j] * al_r[j];
            pr[j] = acc[i][j] * ar_r[j];
        }
        #pragma unroll
        for (int off = 16; off; off >>= 1)
            #pragma unroll
            for (int j = 0; j < 8; j++) {
                pl[j] += __shfl_xor_sync(0xffffffffu, pl[j], off);
                pr[j] += __shfl_xor_sync(0xffffffffu, pr[j], off);
            }
        if (ok && tcol == 0) {
            float* elr = g_el + ((size_t)(p * NN + gr)) * NH;
            float* err = g_er + ((size_t)(p * NN + gr)) * NH;
            *(float4*)(elr)     = make_float4(pl[0], pl[1], pl[2], pl[3]);
            *(float4*)(elr + 4) = make_float4(pl[4], pl[5], pl[6], pl[7]);
            *(float4*)(err)     = make_float4(pr[0], pr[1], pr[2], pr[3]);
            *(float4*)(err + 4) = make_float4(pr[4], pr[5], pr[6], pr[7]);
        }
    }
}

// CSR build: histogram of dst
__global__ void hist_kernel(const void* __restrict__ edges) {
    int p = blockIdx.y;
    int e = blockIdx.x * blockDim.x + threadIdx.x;
    if (e >= NE) return;
    int dst = edge_val(edges, (size_t)2 * p * NE + NE + e);
    atomicAdd(&g_cnt[p * NN + dst], 1);
}

// exclusive prefix sum over counts, one block (1024 thr) per path
__global__ void __launch_bounds__(1024) scan_kernel() {
    __shared__ int wsum[32];
    __shared__ int carry;
    int p = blockIdx.x;
    int tid = threadIdx.x, lane = tid & 31, wid = tid >> 5;
    if (tid == 0) carry = 0;
    __syncthreads();
    for (int base = 0; base < NN; base += 1024) {
        int i = base + tid;
        int v = (i < NN) ? g_cnt[p * NN + i] : 0;
        int x = v;
        #pragma unroll
        for (int o = 1; o < 32; o <<= 1) {
            int y = __shfl_up_sync(0xffffffffu, x, o);
            if (lane >= o) x += y;
        }
        if (lane == 31) wsum[wid] = x;
        __syncthreads();
        if (wid == 0) {
            int w = wsum[lane];
            #pragma unroll
            for (int o = 1; o < 32; o <<= 1) {
                int y = __shfl_up_sync(0xffffffffu, w, o);
                if (lane >= o) w += y;
            }
            wsum[lane] = w;
        }
        __syncthreads();
        int warp_off = (wid == 0) ? 0 : wsum[wid - 1];
        if (i < NN) g_off[p * NN + i] = carry + warp_off + x - v;
        int total = wsum[31];
        __syncthreads();
        if (tid == 0) carry += total;
        __syncthreads();
    }
}

// scatter src ids into CSR slots
__global__ void scatter_kernel(const void* __restrict__ edges) {
    int p = blockIdx.y;
    int e = blockIdx.x * blockDim.x + threadIdx.x;
    if (e >= NE) return;
    size_t base = (size_t)2 * p * NE;
    int src = edge_val(edges, base + e);
    int dst = edge_val(edges, base + NE + e);
    int pos = g_off[p * NN + dst] + atomicAdd(&g_cur[p * NN + dst], 1);
    g_csr[(size_t)p * NE + pos] = src;
}

// fused GAT softmax + aggregation: 64 threads per dst node.
// out[dst] = (1/s) * sum_e exp(leaky(el[src]+er[dst])) * h[src]
__global__ void __launch_bounds__(256) agg_fused() {
    int p = blockIdx.y;
    int g = threadIdx.x >> 6, t = threadIdx.x & 63;
    int dst = blockIdx.x * 4 + g;
    if (dst >= NN) return;
    int head = t >> 3;
    int nd = p * NN + dst;
    int beg = g_off[nd];
    int end = beg + g_cnt[nd];
    float er = g_er[(size_t)nd * NH + head];

    float4 acc = make_float4(0.f, 0.f, 0.f, 0.f);
    float s = 0.f;
    const int* csr = g_csr + (size_t)p * NE;
    for (int k = beg; k < end; k++) {
        int src = csr[k];
        float el = g_el[((size_t)p * NN + src) * NH + head];
        float x = el + er;
        x = x > 0.f ? x : 0.2f * x;
        float w = __expf(fminf(x, 60.f));
        s += w;
        float4 hv = ((const float4*)(g_h + ((size_t)p * NN + src) * HO))[t];
        acc.x += w * hv.x;
        acc.y += w * hv.y;
        acc.z += w * hv.z;
        acc.w += w * hv.w;
    }
    float r = (s > 0.f) ? 1.0f / s : 0.f;
    acc.x *= r; acc.y *= r; acc.z *= r; acc.w *= r;
    ((float4*)(g_out + (size_t)nd * HO))[t] = acc;
}

// semantic: wsum[p] += sum_n tanh(elu(out_p[n]+bias) @ W1 + b1) . w2
// BM=64, BN=128(full), BK=16, thread tile 8x4
__global__ void __launch_bounds__(256) sem_kernel(const float* __restrict__ bias,
                                                  const float* __restrict__ W1,
                                                  const float* __restrict__ b1,
                                                  const float* __restrict__ w2) {
    int p = blockIdx.y;
    int row0 = blockIdx.x * 64;
    __shared__ float As[16][65];
    __shared__ float Bs[16][128];
    __shared__ float red[8];
    int tid = threadIdx.x, tcol = tid & 31, trow = tid >> 5;
    const float* zb = g_out + (size_t)p * NN * HO;
    const float* bp = bias + p * HO;

    float acc[8][4];
    #pragma unroll
    for (int i = 0; i < 8; i++)
        #pragma unroll
        for (int j = 0; j < 4; j++) acc[i][j] = 0.f;

    for (int k0 = 0; k0 < HO; k0 += 16) {
        #pragma unroll
        for (int it = 0; it < 4; it++) {
            int l = tid + it * 256;
            int r = l >> 4, kk = l & 15;
            int gr = row0 + r;
            float v = 0.f;
            if (gr < NN) v = elu_f(zb[(size_t)gr * HO + k0 + kk] + bp[k0 + kk]);
            As[kk][r] = v;
        }
        #pragma unroll
        for (int it = 0; it < 8; it++) {
            int l = tid + it * 256;
            int kk = l >> 7, c = l & 127;
            Bs[kk][c] = W1[(size_t)(k0 + kk) * HID + c];
        }
        __syncthreads();
        #pragma unroll
        for (int kk = 0; kk < 16; kk++) {
            float a[8], b[4];
            #pragma unroll
            for (int i = 0; i < 8; i++) a[i] = As[kk][trow * 8 + i];
            #pragma unroll
            for (int j = 0; j < 4; j++) b[j] = Bs[kk][tcol + 32 * j];
            #pragma unroll
            for (int i = 0; i < 8; i++)
                #pragma unroll
                for (int j = 0; j < 4; j++) acc[i][j] += a[i] * b[j];
        }
        __syncthreads();
    }

    float part = 0.f;
    #pragma unroll
    for (int j = 0; j < 4; j++) {
        int c = tcol + 32 * j;
        float bb = b1[c], ww = w2[c];
        #pragma unroll
        for (int i = 0; i < 8; i++) {
            int gr = row0 + trow * 8 + i;
            if (gr < NN) part += tanh_fast(acc[i][j] + bb) * ww;
        }
    }
    #pragma unroll
    for (int off = 16; off; off >>= 1)
        part += __shfl_down_sync(0xffffffffu, part, off);
    if (tcol == 0) red[trow] = part;
    __syncthreads();
    if (tid == 0) {
        float s = 0.f;
        #pragma unroll
        for (int i = 0; i < 8; i++) s += red[i];
        atomicAdd(&g_wsum[p], s);
    }
}

__global__ void beta_kernel() {
    if (threadIdx.x == 0) {
        float w0 = g_wsum[0] / NN, w1 = g_wsum[1] / NN, w2v = g_wsum[2] / NN;
        float mx = fmaxf(w0, fmaxf(w1, w2v));
        float e0 = __expf(w0 - mx), e1 = __expf(w1 - mx), e2 = __expf(w2v - mx);
        float s = e0 + e1 + e2;
        g_beta[0] = e0 / s;
        g_beta[1] = e1 / s;
        g_beta[2] = e2 / s;
    }
}

__global__ void final_kernel(const float* __restrict__ bias, float* __restrict__ dout) {
    size_t i = (size_t)blockIdx.x * blockDim.x + threadIdx.x;  // float4 index
    size_t total = (size_t)NN * HO / 4;
    if (i >= total) return;
    int c4 = (int)(i & 63);
    float bw[3] = {g_beta[0], g_beta[1], g_beta[2]};
    float4 r = make_float4(0.f, 0.f, 0.f, 0.f);
    #pragma unroll
    for (int p = 0; p < NP; p++) {
        float4 o = ((const float4*)g_out)[(size_t)p * NN * HO / 4 + i];
        const float* bp = bias + p * HO + c4 * 4;
        r.x += bw[p] * elu_f(o.x + bp[0]);
        r.y += bw[p] * elu_f(o.y + bp[1]);
        r.z += bw[p] * elu_f(o.z + bp[2]);
        r.w += bw[p] * elu_f(o.w + bp[3]);
    }
    ((float4*)dout)[i] = r;
}

// ---------------- launch ----------------
extern "C" void kernel_launch(void* const* d_in, const int* in_sizes, int n_in,
                              void* d_out, int out_size) {
    const float* feat  = (const float*)d_in[0];
    const void*  edges = d_in[1];
    const float* Ws    = (const float*)d_in[2];
    const float* al    = (const float*)d_in[3];
    const float* ar    = (const float*)d_in[4];
    const float* bias  = (const float*)d_in[5];
    const float* W1    = (const float*)d_in[6];
    const float* b1    = (const float*)d_in[7];
    const float* w2    = (const float*)d_in[8];
    float* outp = (float*)d_out;

    detect_kernel<<<1, 32>>>((const int*)edges);
    init_small<<<(NP * NN + 255) / 256, 256>>>();

    dim3 gh((NN + 63) / 64, NP);
    gemm_h<<<gh, 256>>>(feat, Ws, al, ar);

    dim3 ge((NE + 255) / 256, NP);
    hist_kernel<<<ge, 256>>>(edges);
    scan_kernel<<<NP, 1024>>>();
    scatter_kernel<<<ge, 256>>>(edges);

    agg_fused<<<dim3((NN + 3) / 4, NP), 256>>>();

    sem_kernel<<<dim3((NN + 63) / 64, NP), 256>>>(bias, W1, b1, w2);
    beta_kernel<<<1, 32>>>();

    final_kernel<<<(int)(((size_t)NN * HO / 4 + 255) / 256), 256>>>(bias, outp);
}

// round 5
// speedup vs baseline: 1.2020x; 1.2020x over previous
#include <cuda_runtime.h>
#include <math.h>

// Problem constants
constexpr int NN  = 50000;   // nodes
constexpr int DIN = 128;     // input feature dim
constexpr int HO  = 256;     // H*O
constexpr int NH  = 8;       // heads
constexpr int NE  = 400000;  // edges per path
constexpr int NP  = 3;       // metapaths
constexpr int HID = 128;     // semantic hidden

// ---------------- scratch (static device globals; no allocation) ----------------
__device__ float g_h  [(size_t)NP * NN * HO];   // per-path projected features
__device__ float g_out[(size_t)NP * NN * HO];   // per-path GAT output accumulator
__device__ float g_el [NP * NN * NH];
__device__ float g_er [NP * NN * NH];
__device__ float g_s  [NP * NN * NH];           // per (dst, head) softmax denominator
__device__ float g_wsum[NP];
__device__ float g_beta[NP];
__device__ int   g_is64;

// ---------------- helpers ----------------
__device__ __forceinline__ float elu_f(float x) { return x > 0.f ? x : expm1f(x); }

__device__ __forceinline__ float tanh_fast(float x) {
    float y;
    asm("tanh.approx.f32 %0, %1;" : "=f"(y) : "f"(x));
    return y;
}

// edges may be int64 (jax x64) or int32 (x64 disabled) — uniform device branch
__device__ __forceinline__ int edge_val(const void* edges, size_t idx) {
    if (g_is64) return (int)(((const long long*)edges)[idx]);
    return ((const int*)edges)[idx];
}

// ---------------- kernels ----------------
__global__ void detect_kernel(const int* e32) {
    if (threadIdx.x == 0 && blockIdx.x == 0) {
        int is64 = 1;
        #pragma unroll
        for (int k = 0; k < 16; k++)
            if (e32[2 * k + 1] != 0) is64 = 0;
        g_is64 = is64;
    }
}

__global__ void init_kernel() {
    size_t i0 = (size_t)blockIdx.x * blockDim.x + threadIdx.x;
    size_t stride = (size_t)gridDim.x * blockDim.x;
    float4 z4 = make_float4(0.f, 0.f, 0.f, 0.f);
    float4* o4 = (float4*)g_out;
    size_t n4 = (size_t)NP * NN * HO / 4;
    for (size_t i = i0; i < n4; i += stride) o4[i] = z4;
    for (size_t i = i0; i < (size_t)NP * NN * NH; i += stride) g_s[i] = 0.f;
    if (i0 < NP) g_wsum[i0] = 0.f;
}

// h_p = feat @ W_p ; BM=64, BN=256(full), BK=16, thread tile 8x8, 256 thr
// Epilogue computes el/er (per node, per head) from register-resident acc.
__global__ void __launch_bounds__(256) gemm_h(const float* __restrict__ feat,
                                              const float* __restrict__ Ws,
                                              const float* __restrict__ al,
                                              const float* __restrict__ ar) {
    int p = blockIdx.y;
    int row0 = blockIdx.x * 64;
    const float* W = Ws + (size_t)p * DIN * HO;
    __shared__ float As[16][65];
    __shared__ float Bs[16][256];
    int tid = threadIdx.x;
    int tcol = tid & 31, trow = tid >> 5;

    float acc[8][8];
    #pragma unroll
    for (int i = 0; i < 8; i++)
        #pragma unroll
        for (int j = 0; j < 8; j++) acc[i][j] = 0.f;

    for (int k0 = 0; k0 < DIN; k0 += 16) {
        #pragma unroll
        for (int it = 0; it < 4; it++) {
            int l = tid + it * 256;
            int r = l >> 4, kk = l & 15;
            int gr = row0 + r;
            As[kk][r] = (gr < NN) ? feat[(size_t)gr * DIN + k0 + kk] : 0.f;
        }
        #pragma unroll
        for (int it = 0; it < 16; it++)
            Bs[it][tid] = W[(size_t)(k0 + it) * HO + tid];
        __syncthreads();
        #pragma unroll
        for (int kk = 0; kk < 16; kk++) {
            float a[8], b[8];
            #pragma unroll
            for (int i = 0; i < 8; i++) a[i] = As[kk][trow * 8 + i];
            #pragma unroll
            for (int j = 0; j < 8; j++) b[j] = Bs[kk][tcol + 32 * j];
            #pragma unroll
            for (int i = 0; i < 8; i++)
                #pragma unroll
                for (int j = 0; j < 8; j++) acc[i][j] += a[i] * b[j];
        }
        __syncthreads();
    }

    // attn vectors: column tcol+32*j lives in head j, o = tcol
    float al_r[8], ar_r[8];
    #pragma unroll
    for (int j = 0; j < 8; j++) {
        al_r[j] = al[p * HO + j * 32 + tcol];
        ar_r[j] = ar[p * HO + j * 32 + tcol];
    }

    #pragma unroll
    for (int i = 0; i < 8; i++) {
        int gr = row0 + trow * 8 + i;
        bool ok = (gr < NN);
        if (ok) {
            float* hrow = g_h + ((size_t)p * NN + gr) * HO;
            #pragma unroll
            for (int j = 0; j < 8; j++) hrow[tcol + 32 * j] = acc[i][j];
        }
        float pl[8], pr[8];
        #pragma unroll
        for (int j = 0; j < 8; j++) {
            pl[j] = acc[i][j] * al_r[j];
            pr[j] = acc[i][j] * ar_r[j];
        }
        #pragma unroll
        for (int off = 16; off; off >>= 1)
            #pragma unroll
            for (int j = 0; j < 8; j++) {
                pl[j] += __shfl_xor_sync(0xffffffffu, pl[j], off);
                pr[j] += __shfl_xor_sync(0xffffffffu, pr[j], off);
            }
        if (ok && tcol == 0) {
            float* elr = g_el + ((size_t)(p * NN + gr)) * NH;
            float* err = g_er + ((size_t)(p * NN + gr)) * NH;
            *(float4*)(elr)     = make_float4(pl[0], pl[1], pl[2], pl[3]);
            *(float4*)(elr + 4) = make_float4(pl[4], pl[5], pl[6], pl[7]);
            *(float4*)(err)     = make_float4(pr[0], pr[1], pr[2], pr[3]);
            *(float4*)(err + 4) = make_float4(pr[4], pr[5], pr[6], pr[7]);
        }
    }
}

// s[dst,head] += exp(leaky(el[src]+er[dst])) ; one thread per (edge, head)
__global__ void edge_sum(const void* __restrict__ edges) {
    int p = blockIdx.y;
    int idx = blockIdx.x * blockDim.x + threadIdx.x;
    if (idx >= NE * NH) return;
    int e = idx >> 3, hd = idx & 7;
    size_t base = (size_t)2 * p * NE;
    int src = edge_val(edges, base + e);
    int dst = edge_val(edges, base + NE + e);
    float x = g_el[((size_t)p * NN + src) * NH + hd] +
              g_er[((size_t)p * NN + dst) * NH + hd];
    x = x > 0.f ? x : 0.2f * x;
    float w = __expf(fminf(x, 60.f));
    atomicAdd(&g_s[((size_t)p * NN + dst) * NH + hd], w);
}

// out[dst] += alpha * h[src] ; 4 edges/block, 64 threads/edge, red.v4.
// alpha recomputed on the fly; exp/rcp deduped to 4 lanes per warp + shuffle.
__global__ void __launch_bounds__(256) agg_kernel(const void* __restrict__ edges) {
    int p = blockIdx.y;
    int g = threadIdx.x >> 6, t = threadIdx.x & 63;
    long long e = (long long)blockIdx.x * 4 + g;
    if (e >= NE) return;
    size_t base = (size_t)2 * p * NE;
    int src = edge_val(edges, base + e);
    int dst = edge_val(edges, base + NE + e);
    int lane = t & 31;
    int wb = (t >> 5) * 4;           // head base covered by this warp
    float alpha_v = 0.f;
    if (lane < 4) {
        int hd = wb + lane;
        float el = g_el[((size_t)p * NN + src) * NH + hd];
        float er = g_er[((size_t)p * NN + dst) * NH + hd];
        float x = el + er;
        x = x > 0.f ? x : 0.2f * x;
        float w = __expf(fminf(x, 60.f));
        float s = g_s[((size_t)p * NN + dst) * NH + hd];
        alpha_v = w * __frcp_rn(s);
    }
    // lane l needs head wb + (l>>3) -> source lane (l>>3)
    float alpha = __shfl_sync(0xffffffffu, alpha_v, lane >> 3);
    float4 hv = ((const float4*)(g_h + ((size_t)p * NN + src) * HO))[t];
    float* o = g_out + ((size_t)p * NN + dst) * HO + t * 4;
    asm volatile("red.global.add.v4.f32 [%0], {%1,%2,%3,%4};"
                 :: "l"(o), "f"(alpha * hv.x), "f"(alpha * hv.y),
                    "f"(alpha * hv.z), "f"(alpha * hv.w)
                 : "memory");
}

// semantic: wsum[p] += sum_n tanh(elu(out_p[n]+bias) @ W1 + b1) . w2
// BM=64, BN=128(full), BK=16, thread tile 8x4
__global__ void __launch_bounds__(256) sem_kernel(const float* __restrict__ bias,
                                                  const float* __restrict__ W1,
                                                  const float* __restrict__ b1,
                                                  const float* __restrict__ w2) {
    int p = blockIdx.y;
    int row0 = blockIdx.x * 64;
    __shared__ float As[16][65];
    __shared__ float Bs[16][128];
    __shared__ float red[8];
    int tid = threadIdx.x, tcol = tid & 31, trow = tid >> 5;
    const float* zb = g_out + (size_t)p * NN * HO;
    const float* bp = bias + p * HO;

    float acc[8][4];
    #pragma unroll
    for (int i = 0; i < 8; i++)
        #pragma unroll
        for (int j = 0; j < 4; j++) acc[i][j] = 0.f;

    for (int k0 = 0; k0 < HO; k0 += 16) {
        #pragma unroll
        for (int it = 0; it < 4; it++) {
            int l = tid + it * 256;
            int r = l >> 4, kk = l & 15;
            int gr = row0 + r;
            float v = 0.f;
            if (gr < NN) v = elu_f(zb[(size_t)gr * HO + k0 + kk] + bp[k0 + kk]);
            As[kk][r] = v;
        }
        #pragma unroll
        for (int it = 0; it < 8; it++) {
            int l = tid + it * 256;
            int kk = l >> 7, c = l & 127;
            Bs[kk][c] = W1[(size_t)(k0 + kk) * HID + c];
        }
        __syncthreads();
        #pragma unroll
        for (int kk = 0; kk < 16; kk++) {
            float a[8], b[4];
            #pragma unroll
            for (int i = 0; i < 8; i++) a[i] = As[kk][trow * 8 + i];
            #pragma unroll
            for (int j = 0; j < 4; j++) b[j] = Bs[kk][tcol + 32 * j];
            #pragma unroll
            for (int i = 0; i < 8; i++)
                #pragma unroll
                for (int j = 0; j < 4; j++) acc[i][j] += a[i] * b[j];
        }
        __syncthreads();
    }

    float part = 0.f;
    #pragma unroll
    for (int j = 0; j < 4; j++) {
        int c = tcol + 32 * j;
        float bb = b1[c], ww = w2[c];
        #pragma unroll
        for (int i = 0; i < 8; i++) {
            int gr = row0 + trow * 8 + i;
            if (gr < NN) part += tanh_fast(acc[i][j] + bb) * ww;
        }
    }
    #pragma unroll
    for (int off = 16; off; off >>= 1)
        part += __shfl_down_sync(0xffffffffu, part, off);
    if (tcol == 0) red[trow] = part;
    __syncthreads();
    if (tid == 0) {
        float s = 0.f;
        #pragma unroll
        for (int i = 0; i < 8; i++) s += red[i];
        atomicAdd(&g_wsum[p], s);
    }
}

__global__ void beta_kernel() {
    if (threadIdx.x == 0) {
        float w0 = g_wsum[0] / NN, w1 = g_wsum[1] / NN, w2v = g_wsum[2] / NN;
        float mx = fmaxf(w0, fmaxf(w1, w2v));
        float e0 = __expf(w0 - mx), e1 = __expf(w1 - mx), e2 = __expf(w2v - mx);
        float s = e0 + e1 + e2;
        g_beta[0] = e0 / s;
        g_beta[1] = e1 / s;
        g_beta[2] = e2 / s;
    }
}

__global__ void final_kernel(const float* __restrict__ bias, float* __restrict__ dout) {
    size_t i = (size_t)blockIdx.x * blockDim.x + threadIdx.x;  // float4 index
    size_t total = (size_t)NN * HO / 4;
    if (i >= total) return;
    int c4 = (int)(i & 63);
    float bw[3] = {g_beta[0], g_beta[1], g_beta[2]};
    float4 r = make_float4(0.f, 0.f, 0.f, 0.f);
    #pragma unroll
    for (int p = 0; p < NP; p++) {
        float4 o = ((const float4*)g_out)[(size_t)p * NN * HO / 4 + i];
        const float* bp = bias + p * HO + c4 * 4;
        r.x += bw[p] * elu_f(o.x + bp[0]);
        r.y += bw[p] * elu_f(o.y + bp[1]);
        r.z += bw[p] * elu_f(o.z + bp[2]);
        r.w += bw[p] * elu_f(o.w + bp[3]);
    }
    ((float4*)dout)[i] = r;
}

// ---------------- launch ----------------
extern "C" void kernel_launch(void* const* d_in, const int* in_sizes, int n_in,
                              void* d_out, int out_size) {
    const float* feat  = (const float*)d_in[0];
    const void*  edges = d_in[1];
    const float* Ws    = (const float*)d_in[2];
    const float* al    = (const float*)d_in[3];
    const float* ar    = (const float*)d_in[4];
    const float* bias  = (const float*)d_in[5];
    const float* W1    = (const float*)d_in[6];
    const float* b1    = (const float*)d_in[7];
    const float* w2    = (const float*)d_in[8];
    float* outp = (float*)d_out;

    detect_kernel<<<1, 32>>>((const int*)edges);
    init_kernel<<<2048, 256>>>();

    dim3 gh((NN + 63) / 64, NP);
    gemm_h<<<gh, 256>>>(feat, Ws, al, ar);

    dim3 ge((NE * NH + 255) / 256, NP);
    edge_sum<<<ge, 256>>>(edges);

    agg_kernel<<<dim3((NE + 3) / 4, NP), 256>>>(edges);

    sem_kernel<<<dim3((NN + 63) / 64, NP), 256>>>(bias, W1, b1, w2);
    beta_kernel<<<1, 32>>>();

    final_kernel<<<(int)(((size_t)NN * HO / 4 + 255) / 256), 256>>>(bias, outp);
}

// round 6
// speedup vs baseline: 1.8435x; 1.5336x over previous
#include <cuda_runtime.h>
#include <math.h>
#include <stdint.h>

// Problem constants
constexpr int NN  = 50000;   // nodes
constexpr int DIN = 128;     // input feature dim
constexpr int HO  = 256;     // H*O
constexpr int NH  = 8;       // heads
constexpr int NE  = 400000;  // edges per path
constexpr int NP  = 3;       // metapaths
constexpr int HID = 128;     // semantic hidden

// ---------------- scratch (static device globals; no allocation) ----------------
__device__ float g_h  [(size_t)NP * NN * HO];   // per-path projected features
__device__ float g_out[(size_t)NP * NN * HO];   // per-path GAT output accumulator
__device__ float g_el [NP * NN * NH];
__device__ float g_er [NP * NN * NH];
__device__ float g_s  [NP * NN * NH];           // per (dst, head) softmax denominator
__device__ float g_wsum[NP];
__device__ float g_beta[NP];
__device__ int   g_is64;

// ---------------- helpers ----------------
__device__ __forceinline__ float elu_f(float x) { return x > 0.f ? x : expm1f(x); }

__device__ __forceinline__ float tanh_fast(float x) {
    float y;
    asm("tanh.approx.f32 %0, %1;" : "=f"(y) : "f"(x));
    return y;
}

__device__ __forceinline__ uint32_t to_tf32(float x) {
    uint32_t r;
    asm("cvt.rna.tf32.f32 %0, %1;" : "=r"(r) : "f"(x));
    return r;
}

// D += A(16x8) * B(8x8), tf32 in, f32 accumulate
__device__ __forceinline__ void mma_tf32(float* c, const uint32_t* a,
                                         uint32_t b0, uint32_t b1) {
    asm volatile(
        "mma.sync.aligned.m16n8k8.row.col.f32.tf32.tf32.f32 "
        "{%0,%1,%2,%3}, {%4,%5,%6,%7}, {%8,%9}, {%0,%1,%2,%3};\n"
        : "+f"(c[0]), "+f"(c[1]), "+f"(c[2]), "+f"(c[3])
        : "r"(a[0]), "r"(a[1]), "r"(a[2]), "r"(a[3]), "r"(b0), "r"(b1));
}

// edges may be int64 (jax x64) or int32 (x64 disabled) — uniform device branch
__device__ __forceinline__ int edge_val(const void* edges, size_t idx) {
    if (g_is64) return (int)(((const long long*)edges)[idx]);
    return ((const int*)edges)[idx];
}

// ---------------- kernels ----------------
__global__ void detect_kernel(const int* e32) {
    if (threadIdx.x == 0 && blockIdx.x == 0) {
        int is64 = 1;
        #pragma unroll
        for (int k = 0; k < 16; k++)
            if (e32[2 * k + 1] != 0) is64 = 0;
        g_is64 = is64;
    }
}

__global__ void init_kernel() {
    size_t i0 = (size_t)blockIdx.x * blockDim.x + threadIdx.x;
    size_t stride = (size_t)gridDim.x * blockDim.x;
    float4 z4 = make_float4(0.f, 0.f, 0.f, 0.f);
    float4* o4 = (float4*)g_out;
    size_t n4 = (size_t)NP * NN * HO / 4;
    for (size_t i = i0; i < n4; i += stride) o4[i] = z4;
    for (size_t i = i0; i < (size_t)NP * NN * NH; i += stride) g_s[i] = 0.f;
    if (i0 < NP) g_wsum[i0] = 0.f;
}

// ===== h_p = feat @ W_p  (tf32 tensor cores) =====
// Block: 64 rows x 256 cols, 8 warps in 2(m) x 4(n), warp tile 32x64.
// BK=32, 4 outer k blocks. Epilogue: store h + fused el/er (2 heads per warp).
constexpr int AS_STR = 36;    // 64 x 36 u32
constexpr int BS_STR = 264;   // 32 x 264 u32

__global__ void __launch_bounds__(256) gemm_h(const float* __restrict__ feat,
                                              const float* __restrict__ Ws,
                                              const float* __restrict__ al,
                                              const float* __restrict__ ar) {
    int p = blockIdx.y;
    int row0 = blockIdx.x * 64;
    const float* W = Ws + (size_t)p * DIN * HO;
    __shared__ uint32_t As[64 * AS_STR];
    __shared__ uint32_t Bs[32 * BS_STR];
    __shared__ float al_s[HO], ar_s[HO];

    int tid = threadIdx.x, lane = tid & 31, warp = tid >> 5;
    int warpm = warp & 1, warpn = warp >> 1;  // 2 x 4
    int gid = lane >> 2, tig = lane & 3;

    al_s[tid] = al[p * HO + tid];
    ar_s[tid] = ar[p * HO + tid];

    float c[2][8][4];
    #pragma unroll
    for (int mt = 0; mt < 2; mt++)
        #pragma unroll
        for (int nt = 0; nt < 8; nt++)
            #pragma unroll
            for (int r = 0; r < 4; r++) c[mt][nt][r] = 0.f;

    for (int kb = 0; kb < 4; kb++) {
        // A tile: 64x32 (512 float4, 2 per thread)
        #pragma unroll
        for (int it = 0; it < 2; it++) {
            int idx = tid + it * 256;
            int r = idx >> 3, c4 = idx & 7;
            int gr = row0 + r;
            float4 v = make_float4(0.f, 0.f, 0.f, 0.f);
            if (gr < NN) v = *(const float4*)(feat + (size_t)gr * DIN + kb * 32 + c4 * 4);
            uint4 u = make_uint4(to_tf32(v.x), to_tf32(v.y), to_tf32(v.z), to_tf32(v.w));
            *(uint4*)(As + r * AS_STR + c4 * 4) = u;
        }
        // B tile: 32x256 (2048 float4, 8 per thread)
        #pragma unroll
        for (int it = 0; it < 8; it++) {
            int idx = tid + it * 256;
            int k = idx >> 6, c4 = idx & 63;
            float4 v = *(const float4*)(W + (size_t)(kb * 32 + k) * HO + c4 * 4);
            uint4 u = make_uint4(to_tf32(v.x), to_tf32(v.y), to_tf32(v.z), to_tf32(v.w));
            *(uint4*)(Bs + k * BS_STR + c4 * 4) = u;
        }
        __syncthreads();
        #pragma unroll
        for (int ks = 0; ks < 4; ks++) {
            int k0 = ks * 8;
            uint32_t a[2][4];
            #pragma unroll
            for (int mt = 0; mt < 2; mt++) {
                int rb = warpm * 32 + mt * 16;
                a[mt][0] = As[(rb + gid) * AS_STR + k0 + tig];
                a[mt][1] = As[(rb + gid + 8) * AS_STR + k0 + tig];
                a[mt][2] = As[(rb + gid) * AS_STR + k0 + tig + 4];
                a[mt][3] = As[(rb + gid + 8) * AS_STR + k0 + tig + 4];
            }
            #pragma unroll
            for (int nt = 0; nt < 8; nt++) {
                int n0 = warpn * 64 + nt * 8;
                uint32_t b0 = Bs[(k0 + tig) * BS_STR + n0 + gid];
                uint32_t b1 = Bs[(k0 + tig + 4) * BS_STR + n0 + gid];
                mma_tf32(c[0][nt], a[0], b0, b1);
                mma_tf32(c[1][nt], a[1], b0, b1);
            }
        }
        __syncthreads();
    }

    // epilogue: store h, fused el/er (warp covers heads warpn*2, warpn*2+1)
    int node[2][2];
    #pragma unroll
    for (int mt = 0; mt < 2; mt++) {
        node[mt][0] = row0 + warpm * 32 + mt * 16 + gid;
        node[mt][1] = node[mt][0] + 8;
    }
    float pl[2][2][2], pr[2][2][2];
    #pragma unroll
    for (int mt = 0; mt < 2; mt++)
        #pragma unroll
        for (int rh = 0; rh < 2; rh++)
            #pragma unroll
            for (int hl = 0; hl < 2; hl++) { pl[mt][rh][hl] = 0.f; pr[mt][rh][hl] = 0.f; }

    #pragma unroll
    for (int nt = 0; nt < 8; nt++) {
        int col0 = warpn * 64 + nt * 8 + 2 * tig;
        int hl = nt >> 2;
        float a0l = al_s[col0], a1l = al_s[col0 + 1];
        float a0r = ar_s[col0], a1r = ar_s[col0 + 1];
        #pragma unroll
        for (int mt = 0; mt < 2; mt++) {
            float v0 = c[mt][nt][0], v1 = c[mt][nt][1];
            float v2 = c[mt][nt][2], v3 = c[mt][nt][3];
            pl[mt][0][hl] += v0 * a0l + v1 * a1l;
            pr[mt][0][hl] += v0 * a0r + v1 * a1r;
            pl[mt][1][hl] += v2 * a0l + v3 * a1l;
            pr[mt][1][hl] += v2 * a0r + v3 * a1r;
            if (node[mt][0] < NN)
                *(float2*)(g_h + ((size_t)p * NN + node[mt][0]) * HO + col0) = make_float2(v0, v1);
            if (node[mt][1] < NN)
                *(float2*)(g_h + ((size_t)p * NN + node[mt][1]) * HO + col0) = make_float2(v2, v3);
        }
    }
    #pragma unroll
    for (int off = 1; off <= 2; off <<= 1)
        #pragma unroll
        for (int mt = 0; mt < 2; mt++)
            #pragma unroll
            for (int rh = 0; rh < 2; rh++)
                #pragma unroll
                for (int hl = 0; hl < 2; hl++) {
                    pl[mt][rh][hl] += __shfl_xor_sync(0xffffffffu, pl[mt][rh][hl], off);
                    pr[mt][rh][hl] += __shfl_xor_sync(0xffffffffu, pr[mt][rh][hl], off);
                }
    if (tig == 0) {
        #pragma unroll
        for (int mt = 0; mt < 2; mt++)
            #pragma unroll
            for (int rh = 0; rh < 2; rh++) {
                int nd = node[mt][rh];
                if (nd < NN) {
                    *(float2*)(g_el + ((size_t)p * NN + nd) * NH + warpn * 2) =
                        make_float2(pl[mt][rh][0], pl[mt][rh][1]);
                    *(float2*)(g_er + ((size_t)p * NN + nd) * NH + warpn * 2) =
                        make_float2(pr[mt][rh][0], pr[mt][rh][1]);
                }
            }
    }
}

// s[dst,head] += exp(leaky(el[src]+er[dst])) ; one thread per (edge, head)
__global__ void edge_sum(const void* __restrict__ edges) {
    int p = blockIdx.y;
    int idx = blockIdx.x * blockDim.x + threadIdx.x;
    if (idx >= NE * NH) return;
    int e = idx >> 3, hd = idx & 7;
    size_t base = (size_t)2 * p * NE;
    int src = edge_val(edges, base + e);
    int dst = edge_val(edges, base + NE + e);
    float x = g_el[((size_t)p * NN + src) * NH + hd] +
              g_er[((size_t)p * NN + dst) * NH + hd];
    x = x > 0.f ? x : 0.2f * x;
    float w = __expf(fminf(x, 60.f));
    atomicAdd(&g_s[((size_t)p * NN + dst) * NH + hd], w);
}

// out[dst] += alpha * h[src] ; 4 edges/block, 64 threads/edge, red.v4.
__global__ void __launch_bounds__(256) agg_kernel(const void* __restrict__ edges) {
    int p = blockIdx.y;
    int g = threadIdx.x >> 6, t = threadIdx.x & 63;
    long long e = (long long)blockIdx.x * 4 + g;
    if (e >= NE) return;
    size_t base = (size_t)2 * p * NE;
    int src = edge_val(edges, base + e);
    int dst = edge_val(edges, base + NE + e);
    int lane = t & 31;
    int wb = (t >> 5) * 4;           // head base covered by this warp
    float alpha_v = 0.f;
    if (lane < 4) {
        int hd = wb + lane;
        float el = g_el[((size_t)p * NN + src) * NH + hd];
        float er = g_er[((size_t)p * NN + dst) * NH + hd];
        float x = el + er;
        x = x > 0.f ? x : 0.2f * x;
        float w = __expf(fminf(x, 60.f));
        float s = g_s[((size_t)p * NN + dst) * NH + hd];
        alpha_v = w * __frcp_rn(s);
    }
    float alpha = __shfl_sync(0xffffffffu, alpha_v, lane >> 3);
    float4 hv = ((const float4*)(g_h + ((size_t)p * NN + src) * HO))[t];
    float* o = g_out + ((size_t)p * NN + dst) * HO + t * 4;
    asm volatile("red.global.add.v4.f32 [%0], {%1,%2,%3,%4};"
                 :: "l"(o), "f"(alpha * hv.x), "f"(alpha * hv.y),
                    "f"(alpha * hv.z), "f"(alpha * hv.w)
                 : "memory");
}

// ===== semantic: wsum[p] += sum_n tanh(elu(out+bias) @ W1 + b1) . w2  (tf32) =====
// Block: 64 rows x 128 cols, 8 warps 2(m) x 4(n), warp tile 32x32. BK=32, 8 k blocks.
constexpr int BS2_STR = 136;  // 32 x 136 u32

__global__ void __launch_bounds__(256) sem_kernel(const float* __restrict__ bias,
                                                  const float* __restrict__ W1,
                                                  const float* __restrict__ b1,
                                                  const float* __restrict__ w2) {
    int p = blockIdx.y;
    int row0 = blockIdx.x * 64;
    __shared__ uint32_t As[64 * AS_STR];
    __shared__ uint32_t Bs[32 * BS2_STR];
    __shared__ float bsum;

    int tid = threadIdx.x, lane = tid & 31, warp = tid >> 5;
    int warpm = warp & 1, warpn = warp >> 1;  // 2 x 4
    int gid = lane >> 2, tig = lane & 3;
    const float* zb = g_out + (size_t)p * NN * HO;
    const float* bp = bias + p * HO;
    if (tid == 0) bsum = 0.f;

    float c[2][4][4];
    #pragma unroll
    for (int mt = 0; mt < 2; mt++)
        #pragma unroll
        for (int nt = 0; nt < 4; nt++)
            #pragma unroll
            for (int r = 0; r < 4; r++) c[mt][nt][r] = 0.f;

    for (int kb = 0; kb < 8; kb++) {
        #pragma unroll
        for (int it = 0; it < 2; it++) {
            int idx = tid + it * 256;
            int r = idx >> 3, c4 = idx & 7;
            int gr = row0 + r;
            float4 v = make_float4(0.f, 0.f, 0.f, 0.f);
            if (gr < NN) {
                v = *(const float4*)(zb + (size_t)gr * HO + kb * 32 + c4 * 4);
                const float* bb = bp + kb * 32 + c4 * 4;
                v.x = elu_f(v.x + bb[0]);
                v.y = elu_f(v.y + bb[1]);
                v.z = elu_f(v.z + bb[2]);
                v.w = elu_f(v.w + bb[3]);
            }
            uint4 u = make_uint4(to_tf32(v.x), to_tf32(v.y), to_tf32(v.z), to_tf32(v.w));
            *(uint4*)(As + r * AS_STR + c4 * 4) = u;
        }
        #pragma unroll
        for (int it = 0; it < 4; it++) {
            int idx = tid + it * 256;
            int k = idx >> 5, c4 = idx & 31;
            float4 v = *(const float4*)(W1 + (size_t)(kb * 32 + k) * HID + c4 * 4);
            uint4 u = make_uint4(to_tf32(v.x), to_tf32(v.y), to_tf32(v.z), to_tf32(v.w));
            *(uint4*)(Bs + k * BS2_STR + c4 * 4) = u;
        }
        __syncthreads();
        #pragma unroll
        for (int ks = 0; ks < 4; ks++) {
            int k0 = ks * 8;
            uint32_t a[2][4];
            #pragma unroll
            for (int mt = 0; mt < 2; mt++) {
                int rb = warpm * 32 + mt * 16;
                a[mt][0] = As[(rb + gid) * AS_STR + k0 + tig];
                a[mt][1] = As[(rb + gid + 8) * AS_STR + k0 + tig];
                a[mt][2] = As[(rb + gid) * AS_STR + k0 + tig + 4];
                a[mt][3] = As[(rb + gid + 8) * AS_STR + k0 + tig + 4];
            }
            #pragma unroll
            for (int nt = 0; nt < 4; nt++) {
                int n0 = warpn * 32 + nt * 8;
                uint32_t b0 = Bs[(k0 + tig) * BS2_STR + n0 + gid];
                uint32_t b1 = Bs[(k0 + tig + 4) * BS2_STR + n0 + gid];
                mma_tf32(c[0][nt], a[0], b0, b1);
                mma_tf32(c[1][nt], a[1], b0, b1);
            }
        }
        __syncthreads();
    }

    float part = 0.f;
    #pragma unroll
    for (int mt = 0; mt < 2; mt++) {
        int rb = row0 + warpm * 32 + mt * 16;
        bool ok0 = (rb + gid) < NN, ok1 = (rb + gid + 8) < NN;
        #pragma unroll
        for (int nt = 0; nt < 4; nt++) {
            int col0 = warpn * 32 + nt * 8 + 2 * tig;
            float b1a = b1[col0], b1b = b1[col0 + 1];
            float w2a = w2[col0], w2b = w2[col0 + 1];
            if (ok0) part += tanh_fast(c[mt][nt][0] + b1a) * w2a +
                             tanh_fast(c[mt][nt][1] + b1b) * w2b;
            if (ok1) part += tanh_fast(c[mt][nt][2] + b1a) * w2a +
                             tanh_fast(c[mt][nt][3] + b1b) * w2b;
        }
    }
    #pragma unroll
    for (int off = 16; off; off >>= 1)
        part += __shfl_xor_sync(0xffffffffu, part, off);
    __syncthreads();
    if (lane == 0) atomicAdd(&bsum, part);
    __syncthreads();
    if (tid == 0) atomicAdd(&g_wsum[p], bsum);
}

__global__ void beta_kernel() {
    if (threadIdx.x == 0) {
        float w0 = g_wsum[0] / NN, w1 = g_wsum[1] / NN, w2v = g_wsum[2] / NN;
        float mx = fmaxf(w0, fmaxf(w1, w2v));
        float e0 = __expf(w0 - mx), e1 = __expf(w1 - mx), e2 = __expf(w2v - mx);
        float s = e0 + e1 + e2;
        g_beta[0] = e0 / s;
        g_beta[1] = e1 / s;
        g_beta[2] = e2 / s;
    }
}

__global__ void final_kernel(const float* __restrict__ bias, float* __restrict__ dout) {
    size_t i = (size_t)blockIdx.x * blockDim.x + threadIdx.x;  // float4 index
    size_t total = (size_t)NN * HO / 4;
    if (i >= total) return;
    int c4 = (int)(i & 63);
    float bw[3] = {g_beta[0], g_beta[1], g_beta[2]};
    float4 r = make_float4(0.f, 0.f, 0.f, 0.f);
    #pragma unroll
    for (int p = 0; p < NP; p++) {
        float4 o = ((const float4*)g_out)[(size_t)p * NN * HO / 4 + i];
        const float* bp = bias + p * HO + c4 * 4;
        r.x += bw[p] * elu_f(o.x + bp[0]);
        r.y += bw[p] * elu_f(o.y + bp[1]);
        r.z += bw[p] * elu_f(o.z + bp[2]);
        r.w += bw[p] * elu_f(o.w + bp[3]);
    }
    ((float4*)dout)[i] = r;
}

// ---------------- launch ----------------
extern "C" void kernel_launch(void* const* d_in, const int* in_sizes, int n_in,
                              void* d_out, int out_size) {
    const float* feat  = (const float*)d_in[0];
    const void*  edges = d_in[1];
    const float* Ws    = (const float*)d_in[2];
    const float* al    = (const float*)d_in[3];
    const float* ar    = (const float*)d_in[4];
    const float* bias  = (const float*)d_in[5];
    const float* W1    = (const float*)d_in[6];
    const float* b1    = (const float*)d_in[7];
    const float* w2    = (const float*)d_in[8];
    float* outp = (float*)d_out;

    detect_kernel<<<1, 32>>>((const int*)edges);
    init_kernel<<<2048, 256>>>();

    dim3 gh((NN + 63) / 64, NP);
    gemm_h<<<gh, 256>>>(feat, Ws, al, ar);

    dim3 ge((NE * NH + 255) / 256, NP);
    edge_sum<<<ge, 256>>>(edges);

    agg_kernel<<<dim3((NE + 3) / 4, NP), 256>>>(edges);

    sem_kernel<<<gh, 256>>>(bias, W1, b1, w2);
    beta_kernel<<<1, 32>>>();

    final_kernel<<<(int)(((size_t)NN * HO / 4 + 255) / 256), 256>>>(bias, outp);
}

// round 8
// speedup vs baseline: 2.6925x; 1.4606x over previous
#include <cuda_runtime.h>
#include <math.h>
#include <stdint.h>

// Problem constants
constexpr int NN  = 50000;   // nodes
constexpr int DIN = 128;     // input feature dim
constexpr int HO  = 256;     // H*O
constexpr int NH  = 8;       // heads
constexpr int NE  = 400000;  // edges per path
constexpr int NP  = 3;       // metapaths
constexpr int HID = 128;     // semantic hidden

// ---------------- scratch (static device globals; no allocation) ----------------
__device__ float g_h  [(size_t)NP * NN * HO];   // per-path projected features
__device__ float g_out[(size_t)NP * NN * HO];   // per-path GAT output (written once)
__device__ float g_el [NP * NN * NH];
__device__ float g_er [NP * NN * NH];
__device__ int   g_cnt[NP * NN];                // in-degree per dst
__device__ int   g_off[NP * NN];                // CSR exclusive offsets
__device__ int   g_cur[NP * NN];                // scatter cursors
__device__ int   g_csr[(size_t)NP * NE];        // src node per CSR slot
__device__ float g_wsum[NP];
__device__ float g_beta[NP];
__device__ int   g_is64;

// ---------------- helpers ----------------
__device__ __forceinline__ float elu_f(float x) { return x > 0.f ? x : expm1f(x); }

__device__ __forceinline__ float tanh_fast(float x) {
    float y;
    asm("tanh.approx.f32 %0, %1;" : "=f"(y) : "f"(x));
    return y;
}

__device__ __forceinline__ uint32_t to_tf32(float x) {
    uint32_t r;
    asm("cvt.rna.tf32.f32 %0, %1;" : "=r"(r) : "f"(x));
    return r;
}

// D += A(16x8) * B(8x8), tf32 in, f32 accumulate
__device__ __forceinline__ void mma_tf32(float* c, const uint32_t* a,
                                         uint32_t b0, uint32_t b1) {
    asm volatile(
        "mma.sync.aligned.m16n8k8.row.col.f32.tf32.tf32.f32 "
        "{%0,%1,%2,%3}, {%4,%5,%6,%7}, {%8,%9}, {%0,%1,%2,%3};\n"
        : "+f"(c[0]), "+f"(c[1]), "+f"(c[2]), "+f"(c[3])
        : "r"(a[0]), "r"(a[1]), "r"(a[2]), "r"(a[3]), "r"(b0), "r"(b1));
}

// edges may be int64 (jax x64) or int32 (x64 disabled) — uniform device branch
__device__ __forceinline__ int edge_val(const void* edges, size_t idx) {
    if (g_is64) return (int)(((const long long*)edges)[idx]);
    return ((const int*)edges)[idx];
}

// ---------------- kernels ----------------
__global__ void detect_kernel(const int* e32) {
    if (threadIdx.x == 0 && blockIdx.x == 0) {
        int is64 = 1;
        #pragma unroll
        for (int k = 0; k < 16; k++)
            if (e32[2 * k + 1] != 0) is64 = 0;
        g_is64 = is64;
    }
}

// zero counters / cursors / wsum (g_out fully written by agg_csr)
__global__ void init_small() {
    int i = blockIdx.x * blockDim.x + threadIdx.x;
    if (i < NP * NN) {
        g_cnt[i] = 0;
        g_cur[i] = 0;
    }
    if (i < NP) g_wsum[i] = 0.f;
}

// ===== h_p = feat @ W_p  (tf32 tensor cores) =====
constexpr int AS_STR = 36;    // 64 x 36 u32
constexpr int BS_STR = 264;   // 32 x 264 u32

__global__ void __launch_bounds__(256) gemm_h(const float* __restrict__ feat,
                                              const float* __restrict__ Ws,
                                              const float* __restrict__ al,
                                              const float* __restrict__ ar) {
    int p = blockIdx.y;
    int row0 = blockIdx.x * 64;
    const float* W = Ws + (size_t)p * DIN * HO;
    __shared__ uint32_t As[64 * AS_STR];
    __shared__ uint32_t Bs[32 * BS_STR];
    __shared__ float al_s[HO], ar_s[HO];

    int tid = threadIdx.x, lane = tid & 31, warp = tid >> 5;
    int warpm = warp & 1, warpn = warp >> 1;  // 2 x 4
    int gid = lane >> 2, tig = lane & 3;

    al_s[tid] = al[p * HO + tid];
    ar_s[tid] = ar[p * HO + tid];

    float c[2][8][4];
    #pragma unroll
    for (int mt = 0; mt < 2; mt++)
        #pragma unroll
        for (int nt = 0; nt < 8; nt++)
            #pragma unroll
            for (int r = 0; r < 4; r++) c[mt][nt][r] = 0.f;

    for (int kb = 0; kb < 4; kb++) {
        #pragma unroll
        for (int it = 0; it < 2; it++) {
            int idx = tid + it * 256;
            int r = idx >> 3, c4 = idx & 7;
            int gr = row0 + r;
            float4 v = make_float4(0.f, 0.f, 0.f, 0.f);
            if (gr < NN) v = *(const float4*)(feat + (size_t)gr * DIN + kb * 32 + c4 * 4);
            uint4 u = make_uint4(to_tf32(v.x), to_tf32(v.y), to_tf32(v.z), to_tf32(v.w));
            *(uint4*)(As + r * AS_STR + c4 * 4) = u;
        }
        #pragma unroll
        for (int it = 0; it < 8; it++) {
            int idx = tid + it * 256;
            int k = idx >> 6, c4 = idx & 63;
            float4 v = *(const float4*)(W + (size_t)(kb * 32 + k) * HO + c4 * 4);
            uint4 u = make_uint4(to_tf32(v.x), to_tf32(v.y), to_tf32(v.z), to_tf32(v.w));
            *(uint4*)(Bs + k * BS_STR + c4 * 4) = u;
        }
        __syncthreads();
        #pragma unroll
        for (int ks = 0; ks < 4; ks++) {
            int k0 = ks * 8;
            uint32_t a[2][4];
            #pragma unroll
            for (int mt = 0; mt < 2; mt++) {
                int rb = warpm * 32 + mt * 16;
                a[mt][0] = As[(rb + gid) * AS_STR + k0 + tig];
                a[mt][1] = As[(rb + gid + 8) * AS_STR + k0 + tig];
                a[mt][2] = As[(rb + gid) * AS_STR + k0 + tig + 4];
                a[mt][3] = As[(rb + gid + 8) * AS_STR + k0 + tig + 4];
            }
            #pragma unroll
            for (int nt = 0; nt < 8; nt++) {
                int n0 = warpn * 64 + nt * 8;
                uint32_t b0 = Bs[(k0 + tig) * BS_STR + n0 + gid];
                uint32_t b1 = Bs[(k0 + tig + 4) * BS_STR + n0 + gid];
                mma_tf32(c[0][nt], a[0], b0, b1);
                mma_tf32(c[1][nt], a[1], b0, b1);
            }
        }
        __syncthreads();
    }

    // epilogue: store h, fused el/er (warp covers heads warpn*2, warpn*2+1)
    int node[2][2];
    #pragma unroll
    for (int mt = 0; mt < 2; mt++) {
        node[mt][0] = row0 + warpm * 32 + mt * 16 + gid;
        node[mt][1] = node[mt][0] + 8;
    }
    float pl[2][2][2], pr[2][2][2];
    #pragma unroll
    for (int mt = 0; mt < 2; mt++)
        #pragma unroll
        for (int rh = 0; rh < 2; rh++)
            #pragma unroll
            for (int hl = 0; hl < 2; hl++) { pl[mt][rh][hl] = 0.f; pr[mt][rh][hl] = 0.f; }

    #pragma unroll
    for (int nt = 0; nt < 8; nt++) {
        int col0 = warpn * 64 + nt * 8 + 2 * tig;
        int hl = nt >> 2;
        float a0l = al_s[col0], a1l = al_s[col0 + 1];
        float a0r = ar_s[col0], a1r = ar_s[col0 + 1];
        #pragma unroll
        for (int mt = 0; mt < 2; mt++) {
            float v0 = c[mt][nt][0], v1 = c[mt][nt][1];
            float v2 = c[mt][nt][2], v3 = c[mt][nt][3];
            pl[mt][0][hl] += v0 * a0l + v1 * a1l;
            pr[mt][0][hl] += v0 * a0r + v1 * a1r;
            pl[mt][1][hl] += v2 * a0l + v3 * a1l;
            pr[mt][1][hl] += v2 * a0r + v3 * a1r;
            if (node[mt][0] < NN)
                *(float2*)(g_h + ((size_t)p * NN + node[mt][0]) * HO + col0) = make_float2(v0, v1);
            if (node[mt][1] < NN)
                *(float2*)(g_h + ((size_t)p * NN + node[mt][1]) * HO + col0) = make_float2(v2, v3);
        }
    }
    #pragma unroll
    for (int off = 1; off <= 2; off <<= 1)
        #pragma unroll
        for (int mt = 0; mt < 2; mt++)
            #pragma unroll
            for (int rh = 0; rh < 2; rh++)
                #pragma unroll
                for (int hl = 0; hl < 2; hl++) {
                    pl[mt][rh][hl] += __shfl_xor_sync(0xffffffffu, pl[mt][rh][hl], off);
                    pr[mt][rh][hl] += __shfl_xor_sync(0xffffffffu, pr[mt][rh][hl], off);
                }
    if (tig == 0) {
        #pragma unroll
        for (int mt = 0; mt < 2; mt++)
            #pragma unroll
            for (int rh = 0; rh < 2; rh++) {
                int nd = node[mt][rh];
                if (nd < NN) {
                    *(float2*)(g_el + ((size_t)p * NN + nd) * NH + warpn * 2) =
                        make_float2(pl[mt][rh][0], pl[mt][rh][1]);
                    *(float2*)(g_er + ((size_t)p * NN + nd) * NH + warpn * 2) =
                        make_float2(pr[mt][rh][0], pr[mt][rh][1]);
                }
            }
    }
}

// CSR build: histogram of dst
__global__ void hist_kernel(const void* __restrict__ edges) {
    int p = blockIdx.y;
    int e = blockIdx.x * blockDim.x + threadIdx.x;
    if (e >= NE) return;
    int dst = edge_val(edges, (size_t)2 * p * NE + NE + e);
    atomicAdd(&g_cnt[p * NN + dst], 1);
}

// exclusive prefix sum over counts, one block (1024 thr) per path
__global__ void __launch_bounds__(1024) scan_kernel() {
    __shared__ int wsum[32];
    __shared__ int carry;
    int p = blockIdx.x;
    int tid = threadIdx.x, lane = tid & 31, wid = tid >> 5;
    if (tid == 0) carry = 0;
    __syncthreads();
    for (int base = 0; base < NN; base += 1024) {
        int i = base + tid;
        int v = (i < NN) ? g_cnt[p * NN + i] : 0;
        int x = v;
        #pragma unroll
        for (int o = 1; o < 32; o <<= 1) {
            int y = __shfl_up_sync(0xffffffffu, x, o);
            if (lane >= o) x += y;
        }
        if (lane == 31) wsum[wid] = x;
        __syncthreads();
        if (wid == 0) {
            int w = wsum[lane];
            #pragma unroll
            for (int o = 1; o < 32; o <<= 1) {
                int y = __shfl_up_sync(0xffffffffu, w, o);
                if (lane >= o) w += y;
            }
            wsum[lane] = w;
        }
        __syncthreads();
        int warp_off = (wid == 0) ? 0 : wsum[wid - 1];
        if (i < NN) g_off[p * NN + i] = carry + warp_off + x - v;
        int total = wsum[31];
        __syncthreads();
        if (tid == 0) carry += total;
        __syncthreads();
    }
}

// scatter src ids into CSR slots
__global__ void scatter_kernel(const void* __restrict__ edges) {
    int p = blockIdx.y;
    int e = blockIdx.x * blockDim.x + threadIdx.x;
    if (e >= NE) return;
    size_t base = (size_t)2 * p * NE;
    int src = edge_val(edges, base + e);
    int dst = edge_val(edges, base + NE + e);
    int pos = g_off[p * NN + dst] + atomicAdd(&g_cur[p * NN + dst], 1);
    g_csr[(size_t)p * NE + pos] = src;
}

// ===== CSR aggregation: one WARP per dst, warp-synchronous two-phase softmax =====
// lane covers cols lane*8 .. lane*8+7 (head = lane>>2).
// Phase A (per chunk of <=32 edges): lanes < csz stage w[head][edge] in smem.
// Phase B: all lanes accumulate sum(w * h[src]) with unroll-by-2 gather.
__global__ void __launch_bounds__(256) agg_csr() {
    int p = blockIdx.y;
    int wid = threadIdx.x >> 5, lane = threadIdx.x & 31;
    int dst = blockIdx.x * 8 + wid;
    if (dst >= NN) return;
    __shared__ float s_w[8][NH][33];
    __shared__ int   s_src[8][32];

    int nd = p * NN + dst;
    int beg = g_off[nd], deg = g_cnt[nd];
    int head = lane >> 2;

    // er row for this dst (uniform across warp)
    float4 er0 = *(const float4*)(g_er + (size_t)nd * NH);
    float4 er1 = *(const float4*)(g_er + (size_t)nd * NH + 4);
    float erv[8] = {er0.x, er0.y, er0.z, er0.w, er1.x, er1.y, er1.z, er1.w};

    float4 a0 = make_float4(0.f, 0.f, 0.f, 0.f);
    float4 a1 = make_float4(0.f, 0.f, 0.f, 0.f);
    float s = 0.f;
    const int* csr = g_csr + (size_t)p * NE + beg;
    const float* hbase = g_h + (size_t)p * NN * HO;

    for (int c0 = 0; c0 < deg; c0 += 32) {
        int csz = min(32, deg - c0);
        if (lane < csz) {
            int src = csr[c0 + lane];
            s_src[wid][lane] = src;
            const float* el = g_el + ((size_t)p * NN + src) * NH;
            float4 e0 = *(const float4*)el;
            float4 e1 = *(const float4*)(el + 4);
            float elv[8] = {e0.x, e0.y, e0.z, e0.w, e1.x, e1.y, e1.z, e1.w};
            #pragma unroll
            for (int j = 0; j < 8; j++) {
                float x = elv[j] + erv[j];
                x = x > 0.f ? x : 0.2f * x;
                s_w[wid][j][lane] = __expf(fminf(x, 60.f));
            }
        }
        __syncwarp();
        int k = 0;
        for (; k + 2 <= csz; k += 2) {
            int s0 = s_src[wid][k], s1 = s_src[wid][k + 1];
            float w0 = s_w[wid][head][k], w1 = s_w[wid][head][k + 1];
            const float4* h0 = (const float4*)(hbase + (size_t)s0 * HO) + lane * 2;
            const float4* h1 = (const float4*)(hbase + (size_t)s1 * HO) + lane * 2;
            float4 x0 = h0[0], x1 = h0[1], y0 = h1[0], y1 = h1[1];
            s += w0 + w1;
            a0.x += w0 * x0.x + w1 * y0.x;
            a0.y += w0 * x0.y + w1 * y0.y;
            a0.z += w0 * x0.z + w1 * y0.z;
            a0.w += w0 * x0.w + w1 * y0.w;
            a1.x += w0 * x1.x + w1 * y1.x;
            a1.y += w0 * x1.y + w1 * y1.y;
            a1.z += w0 * x1.z + w1 * y1.z;
            a1.w += w0 * x1.w + w1 * y1.w;
        }
        if (k < csz) {
            int s0 = s_src[wid][k];
            float w0 = s_w[wid][head][k];
            const float4* h0 = (const float4*)(hbase + (size_t)s0 * HO) + lane * 2;
            float4 x0 = h0[0], x1 = h0[1];
            s += w0;
            a0.x += w0 * x0.x; a0.y += w0 * x0.y; a0.z += w0 * x0.z; a0.w += w0 * x0.w;
            a1.x += w0 * x1.x; a1.y += w0 * x1.y; a1.z += w0 * x1.z; a1.w += w0 * x1.w;
        }
        __syncwarp();
    }

    float r = (s > 0.f) ? 1.0f / s : 0.f;
    a0.x *= r; a0.y *= r; a0.z *= r; a0.w *= r;
    a1.x *= r; a1.y *= r; a1.z *= r; a1.w *= r;
    float4* orow = (float4*)(g_out + (size_t)nd * HO) + lane * 2;
    orow[0] = a0;
    orow[1] = a1;
}

// ===== semantic: wsum[p] += sum_n tanh(elu(out+bias) @ W1 + b1) . w2  (tf32) =====
constexpr int BS2_STR = 136;  // 32 x 136 u32

__global__ void __launch_bounds__(256) sem_kernel(const float* __restrict__ bias,
                                                  const float* __restrict__ W1,
                                                  const float* __restrict__ b1,
                                                  const float* __restrict__ w2) {
    int p = blockIdx.y;
    int row0 = blockIdx.x * 64;
    __shared__ uint32_t As[64 * AS_STR];
    __shared__ uint32_t Bs[32 * BS2_STR];
    __shared__ float bsum;

    int tid = threadIdx.x, lane = tid & 31, warp = tid >> 5;
    int warpm = warp & 1, warpn = warp >> 1;  // 2 x 4
    int gid = lane >> 2, tig = lane & 3;
    const float* zb = g_out + (size_t)p * NN * HO;
    const float* bp = bias + p * HO;
    if (tid == 0) bsum = 0.f;

    float c[2][4][4];
    #pragma unroll
    for (int mt = 0; mt < 2; mt++)
        #pragma unroll
        for (int nt = 0; nt < 4; nt++)
            #pragma unroll
            for (int r = 0; r < 4; r++) c[mt][nt][r] = 0.f;

    for (int kb = 0; kb < 8; kb++) {
        #pragma unroll
        for (int it = 0; it < 2; it++) {
            int idx = tid + it * 256;
            int r = idx >> 3, c4 = idx & 7;
            int gr = row0 + r;
            float4 v = make_float4(0.f, 0.f, 0.f, 0.f);
            if (gr < NN) {
                v = *(const float4*)(zb + (size_t)gr * HO + kb * 32 + c4 * 4);
                const float* bb = bp + kb * 32 + c4 * 4;
                v.x = elu_f(v.x + bb[0]);
                v.y = elu_f(v.y + bb[1]);
                v.z = elu_f(v.z + bb[2]);
                v.w = elu_f(v.w + bb[3]);
            }
            uint4 u = make_uint4(to_tf32(v.x), to_tf32(v.y), to_tf32(v.z), to_tf32(v.w));
            *(uint4*)(As + r * AS_STR + c4 * 4) = u;
        }
        #pragma unroll
        for (int it = 0; it < 4; it++) {
            int idx = tid + it * 256;
            int k = idx >> 5, c4 = idx & 31;
            float4 v = *(const float4*)(W1 + (size_t)(kb * 32 + k) * HID + c4 * 4);
            uint4 u = make_uint4(to_tf32(v.x), to_tf32(v.y), to_tf32(v.z), to_tf32(v.w));
            *(uint4*)(Bs + k * BS2_STR + c4 * 4) = u;
        }
        __syncthreads();
        #pragma unroll
        for (int ks = 0; ks < 4; ks++) {
            int k0 = ks * 8;
            uint32_t a[2][4];
            #pragma unroll
            for (int mt = 0; mt < 2; mt++) {
                int rb = warpm * 32 + mt * 16;
                a[mt][0] = As[(rb + gid) * AS_STR + k0 + tig];
                a[mt][1] = As[(rb + gid + 8) * AS_STR + k0 + tig];
                a[mt][2] = As[(rb + gid) * AS_STR + k0 + tig + 4];
                a[mt][3] = As[(rb + gid + 8) * AS_STR + k0 + tig + 4];
            }
            #pragma unroll
            for (int nt = 0; nt < 4; nt++) {
                int n0 = warpn * 32 + nt * 8;
                uint32_t b0 = Bs[(k0 + tig) * BS2_STR + n0 + gid];
                uint32_t b1 = Bs[(k0 + tig + 4) * BS2_STR + n0 + gid];
                mma_tf32(c[0][nt], a[0], b0, b1);
                mma_tf32(c[1][nt], a[1], b0, b1);
            }
        }
        __syncthreads();
    }

    float part = 0.f;
    #pragma unroll
    for (int mt = 0; mt < 2; mt++) {
        int rb = row0 + warpm * 32 + mt * 16;
        bool ok0 = (rb + gid) < NN, ok1 = (rb + gid + 8) < NN;
        #pragma unroll
        for (int nt = 0; nt < 4; nt++) {
            int col0 = warpn * 32 + nt * 8 + 2 * tig;
            float b1a = b1[col0], b1b = b1[col0 + 1];
            float w2a = w2[col0], w2b = w2[col0 + 1];
            if (ok0) part += tanh_fast(c[mt][nt][0] + b1a) * w2a +
                             tanh_fast(c[mt][nt][1] + b1b) * w2b;
            if (ok1) part += tanh_fast(c[mt][nt][2] + b1a) * w2a +
                             tanh_fast(c[mt][nt][3] + b1b) * w2b;
        }
    }
    #pragma unroll
    for (int off = 16; off; off >>= 1)
        part += __shfl_xor_sync(0xffffffffu, part, off);
    __syncthreads();
    if (lane == 0) atomicAdd(&bsum, part);
    __syncthreads();
    if (tid == 0) atomicAdd(&g_wsum[p], bsum);
}

__global__ void beta_kernel() {
    if (threadIdx.x == 0) {
        float w0 = g_wsum[0] / NN, w1 = g_wsum[1] / NN, w2v = g_wsum[2] / NN;
        float mx = fmaxf(w0, fmaxf(w1, w2v));
        float e0 = __expf(w0 - mx), e1 = __expf(w1 - mx), e2 = __expf(w2v - mx);
        float s = e0 + e1 + e2;
        g_beta[0] = e0 / s;
        g_beta[1] = e1 / s;
        g_beta[2] = e2 / s;
    }
}

__global__ void final_kernel(const float* __restrict__ bias, float* __restrict__ dout) {
    size_t i = (size_t)blockIdx.x * blockDim.x + threadIdx.x;  // float4 index
    size_t total = (size_t)NN * HO / 4;
    if (i >= total) return;
    int c4 = (int)(i & 63);
    float bw[3] = {g_beta[0], g_beta[1], g_beta[2]};
    float4 r = make_float4(0.f, 0.f, 0.f, 0.f);
    #pragma unroll
    for (int p = 0; p < NP; p++) {
        float4 o = ((const float4*)g_out)[(size_t)p * NN * HO / 4 + i];
        const float* bp = bias + p * HO + c4 * 4;
        r.x += bw[p] * elu_f(o.x + bp[0]);
        r.y += bw[p] * elu_f(o.y + bp[1]);
        r.z += bw[p] * elu_f(o.z + bp[2]);
        r.w += bw[p] * elu_f(o.w + bp[3]);
    }
    ((float4*)dout)[i] = r;
}

// ---------------- launch ----------------
extern "C" void kernel_launch(void* const* d_in, const int* in_sizes, int n_in,
                              void* d_out, int out_size) {
    const float* feat  = (const float*)d_in[0];
    const void*  edges = d_in[1];
    const float* Ws    = (const float*)d_in[2];
    const float* al    = (const float*)d_in[3];
    const float* ar    = (const float*)d_in[4];
    const float* bias  = (const float*)d_in[5];
    const float* W1    = (const float*)d_in[6];
    const float* b1    = (const float*)d_in[7];
    const float* w2    = (const float*)d_in[8];
    float* outp = (float*)d_out;

    detect_kernel<<<1, 32>>>((const int*)edges);
    init_small<<<(NP * NN + 255) / 256, 256>>>();

    dim3 gh((NN + 63) / 64, NP);
    gemm_h<<<gh, 256>>>(feat, Ws, al, ar);

    dim3 ge((NE + 255) / 256, NP);
    hist_kernel<<<ge, 256>>>(edges);
    scan_kernel<<<NP, 1024>>>();
    scatter_kernel<<<ge, 256>>>(edges);

    agg_csr<<<dim3((NN + 7) / 8, NP), 256>>>();

    sem_kernel<<<gh, 256>>>(bias, W1, b1, w2);
    beta_kernel<<<1, 32>>>();

    final_kernel<<<(int)(((size_t)NN * HO / 4 + 255) / 256), 256>>>(bias, outp);
}

// round 12
// speedup vs baseline: 2.9926x; 1.1114x over previous
#include <cuda_runtime.h>
#include <cuda_fp16.h>
#include <math.h>
#include <stdint.h>

// Problem constants
constexpr int NN  = 50000;   // nodes
constexpr int DIN = 128;     // input feature dim
constexpr int HO  = 256;     // H*O
constexpr int NH  = 8;       // heads
constexpr int NE  = 400000;  // edges per path
constexpr int NP  = 3;       // metapaths
constexpr int HID = 128;     // semantic hidden

// ---------------- scratch (static device globals; no allocation) ----------------
__device__ __half g_h [(size_t)NP * NN * HO];   // per-path projected features (fp16, L2-resident)
__device__ float g_out[(size_t)NP * NN * HO];   // per-path GAT output (written once)
__device__ float g_el [NP * NN * NH];
__device__ float g_er [NP * NN * NH];
__device__ int   g_cnt[NP * NN];                // in-degree per dst
__device__ int   g_off[NP * NN];                // CSR exclusive offsets
__device__ int   g_cur[NP * NN];                // scatter cursors
__device__ int   g_csr[(size_t)NP * NE];        // src node per CSR slot
__device__ float g_wsum[NP];
__device__ float g_beta[NP];
__device__ int   g_is64;

// ---------------- helpers ----------------
__device__ __forceinline__ float elu_f(float x) { return x > 0.f ? x : expm1f(x); }

__device__ __forceinline__ float tanh_fast(float x) {
    float y;
    asm("tanh.approx.f32 %0, %1;" : "=f"(y) : "f"(x));
    return y;
}

__device__ __forceinline__ uint32_t to_tf32(float x) {
    uint32_t r;
    asm("cvt.rna.tf32.f32 %0, %1;" : "=r"(r) : "f"(x));
    return r;
}

// D += A(16x8) * B(8x8), tf32 in, f32 accumulate
__device__ __forceinline__ void mma_tf32(float* c, const uint32_t* a,
                                         uint32_t b0, uint32_t b1) {
    asm volatile(
        "mma.sync.aligned.m16n8k8.row.col.f32.tf32.tf32.f32 "
        "{%0,%1,%2,%3}, {%4,%5,%6,%7}, {%8,%9}, {%0,%1,%2,%3};\n"
        : "+f"(c[0]), "+f"(c[1]), "+f"(c[2]), "+f"(c[3])
        : "r"(a[0]), "r"(a[1]), "r"(a[2]), "r"(a[3]), "r"(b0), "r"(b1));
}

// edges may be int64 (jax x64) or int32 (x64 disabled) — uniform device branch
__device__ __forceinline__ int edge_val(const void* edges, size_t idx) {
    if (g_is64) return (int)(((const long long*)edges)[idx]);
    return ((const int*)edges)[idx];
}

// ---------------- kernels ----------------
__global__ void detect_kernel(const int* e32) {
    if (threadIdx.x == 0 && blockIdx.x == 0) {
        int is64 = 1;
        #pragma unroll
        for (int k = 0; k < 16; k++)
            if (e32[2 * k + 1] != 0) is64 = 0;
        g_is64 = is64;
    }
}

// zero counters / cursors / wsum (g_out fully written by agg_csr)
__global__ void init_small() {
    int i = blockIdx.x * blockDim.x + threadIdx.x;
    if (i < NP * NN) {
        g_cnt[i] = 0;
        g_cur[i] = 0;
    }
    if (i < NP) g_wsum[i] = 0.f;
}

// ===== h_p = feat @ W_p  (tf32 tensor cores), h stored as fp16 =====
constexpr int AS_STR = 36;    // 64 x 36 u32
constexpr int BS_STR = 264;   // 32 x 264 u32

__global__ void __launch_bounds__(256) gemm_h(const float* __restrict__ feat,
                                              const float* __restrict__ Ws,
                                              const float* __restrict__ al,
                                              const float* __restrict__ ar) {
    int p = blockIdx.y;
    int row0 = blockIdx.x * 64;
    const float* W = Ws + (size_t)p * DIN * HO;
    __shared__ uint32_t As[64 * AS_STR];
    __shared__ uint32_t Bs[32 * BS_STR];
    __shared__ float al_s[HO], ar_s[HO];

    int tid = threadIdx.x, lane = tid & 31, warp = tid >> 5;
    int warpm = warp & 1, warpn = warp >> 1;  // 2 x 4
    int gid = lane >> 2, tig = lane & 3;

    al_s[tid] = al[p * HO + tid];
    ar_s[tid] = ar[p * HO + tid];

    float c[2][8][4];
    #pragma unroll
    for (int mt = 0; mt < 2; mt++)
        #pragma unroll
        for (int nt = 0; nt < 8; nt++)
            #pragma unroll
            for (int r = 0; r < 4; r++) c[mt][nt][r] = 0.f;

    for (int kb = 0; kb < 4; kb++) {
        #pragma unroll
        for (int it = 0; it < 2; it++) {
            int idx = tid + it * 256;
            int r = idx >> 3, c4 = idx & 7;
            int gr = row0 + r;
            float4 v = make_float4(0.f, 0.f, 0.f, 0.f);
            if (gr < NN) v = *(const float4*)(feat + (size_t)gr * DIN + kb * 32 + c4 * 4);
            uint4 u = make_uint4(to_tf32(v.x), to_tf32(v.y), to_tf32(v.z), to_tf32(v.w));
            *(uint4*)(As + r * AS_STR + c4 * 4) = u;
        }
        #pragma unroll
        for (int it = 0; it < 8; it++) {
            int idx = tid + it * 256;
            int k = idx >> 6, c4 = idx & 63;
            float4 v = *(const float4*)(W + (size_t)(kb * 32 + k) * HO + c4 * 4);
            uint4 u = make_uint4(to_tf32(v.x), to_tf32(v.y), to_tf32(v.z), to_tf32(v.w));
            *(uint4*)(Bs + k * BS_STR + c4 * 4) = u;
        }
        __syncthreads();
        #pragma unroll
        for (int ks = 0; ks < 4; ks++) {
            int k0 = ks * 8;
            uint32_t a[2][4];
            #pragma unroll
            for (int mt = 0; mt < 2; mt++) {
                int rb = warpm * 32 + mt * 16;
                a[mt][0] = As[(rb + gid) * AS_STR + k0 + tig];
                a[mt][1] = As[(rb + gid + 8) * AS_STR + k0 + tig];
                a[mt][2] = As[(rb + gid) * AS_STR + k0 + tig + 4];
                a[mt][3] = As[(rb + gid + 8) * AS_STR + k0 + tig + 4];
            }
            #pragma unroll
            for (int nt = 0; nt < 8; nt++) {
                int n0 = warpn * 64 + nt * 8;
                uint32_t b0 = Bs[(k0 + tig) * BS_STR + n0 + gid];
                uint32_t b1 = Bs[(k0 + tig + 4) * BS_STR + n0 + gid];
                mma_tf32(c[0][nt], a[0], b0, b1);
                mma_tf32(c[1][nt], a[1], b0, b1);
            }
        }
        __syncthreads();
    }

    // epilogue: store h (fp16), fused el/er (warp covers heads warpn*2, warpn*2+1)
    int node[2][2];
    #pragma unroll
    for (int mt = 0; mt < 2; mt++) {
        node[mt][0] = row0 + warpm * 32 + mt * 16 + gid;
        node[mt][1] = node[mt][0] + 8;
    }
    float pl[2][2][2], pr[2][2][2];
    #pragma unroll
    for (int mt = 0; mt < 2; mt++)
        #pragma unroll
        for (int rh = 0; rh < 2; rh++)
            #pragma unroll
            for (int hl = 0; hl < 2; hl++) { pl[mt][rh][hl] = 0.f; pr[mt][rh][hl] = 0.f; }

    #pragma unroll
    for (int nt = 0; nt < 8; nt++) {
        int col0 = warpn * 64 + nt * 8 + 2 * tig;
        int hl = nt >> 2;
        float a0l = al_s[col0], a1l = al_s[col0 + 1];
        float a0r = ar_s[col0], a1r = ar_s[col0 + 1];
        #pragma unroll
        for (int mt = 0; mt < 2; mt++) {
            float v0 = c[mt][nt][0], v1 = c[mt][nt][1];
            float v2 = c[mt][nt][2], v3 = c[mt][nt][3];
            pl[mt][0][hl] += v0 * a0l + v1 * a1l;
            pr[mt][0][hl] += v0 * a0r + v1 * a1r;
            pl[mt][1][hl] += v2 * a0l + v3 * a1l;
            pr[mt][1][hl] += v2 * a0r + v3 * a1r;
            if (node[mt][0] < NN)
                *(half2*)(g_h + ((size_t)p * NN + node[mt][0]) * HO + col0) =
                    __floats2half2_rn(v0, v1);
            if (node[mt][1] < NN)
                *(half2*)(g_h + ((size_t)p * NN + node[mt][1]) * HO + col0) =
                    __floats2half2_rn(v2, v3);
        }
    }
    #pragma unroll
    for (int off = 1; off <= 2; off <<= 1)
        #pragma unroll
        for (int mt = 0; mt < 2; mt++)
            #pragma unroll
            for (int rh = 0; rh < 2; rh++)
                #pragma unroll
                for (int hl = 0; hl < 2; hl++) {
                    pl[mt][rh][hl] += __shfl_xor_sync(0xffffffffu, pl[mt][rh][hl], off);
                    pr[mt][rh][hl] += __shfl_xor_sync(0xffffffffu, pr[mt][rh][hl], off);
                }
    if (tig == 0) {
        #pragma unroll
        for (int mt = 0; mt < 2; mt++)
            #pragma unroll
            for (int rh = 0; rh < 2; rh++) {
                int nd = node[mt][rh];
                if (nd < NN) {
                    *(float2*)(g_el + ((size_t)p * NN + nd) * NH + warpn * 2) =
                        make_float2(pl[mt][rh][0], pl[mt][rh][1]);
                    *(float2*)(g_er + ((size_t)p * NN + nd) * NH + warpn * 2) =
                        make_float2(pr[mt][rh][0], pr[mt][rh][1]);
                }
            }
    }
}

// CSR build: histogram of dst
__global__ void hist_kernel(const void* __restrict__ edges) {
    int p = blockIdx.y;
    int e = blockIdx.x * blockDim.x + threadIdx.x;
    if (e >= NE) return;
    int dst = edge_val(edges, (size_t)2 * p * NE + NE + e);
    atomicAdd(&g_cnt[p * NN + dst], 1);
}

// exclusive prefix sum over counts, one block (1024 thr) per path
__global__ void __launch_bounds__(1024) scan_kernel() {
    __shared__ int wsum[32];
    __shared__ int carry;
    int p = blockIdx.x;
    int tid = threadIdx.x, lane = tid & 31, wid = tid >> 5;
    if (tid == 0) carry = 0;
    __syncthreads();
    for (int base = 0; base < NN; base += 1024) {
        int i = base + tid;
        int v = (i < NN) ? g_cnt[p * NN + i] : 0;
        int x = v;
        #pragma unroll
        for (int o = 1; o < 32; o <<= 1) {
            int y = __shfl_up_sync(0xffffffffu, x, o);
            if (lane >= o) x += y;
        }
        if (lane == 31) wsum[wid] = x;
        __syncthreads();
        if (wid == 0) {
            int w = wsum[lane];
            #pragma unroll
            for (int o = 1; o < 32; o <<= 1) {
                int y = __shfl_up_sync(0xffffffffu, w, o);
                if (lane >= o) w += y;
            }
            wsum[lane] = w;
        }
        __syncthreads();
        int warp_off = (wid == 0) ? 0 : wsum[wid - 1];
        if (i < NN) g_off[p * NN + i] = carry + warp_off + x - v;
        int total = wsum[31];
        __syncthreads();
        if (tid == 0) carry += total;
        __syncthreads();
    }
}

// scatter src ids into CSR slots
__global__ void scatter_kernel(const void* __restrict__ edges) {
    int p = blockIdx.y;
    int e = blockIdx.x * blockDim.x + threadIdx.x;
    if (e >= NE) return;
    size_t base = (size_t)2 * p * NE;
    int src = edge_val(edges, base + e);
    int dst = edge_val(edges, base + NE + e);
    int pos = g_off[p * NN + dst] + atomicAdd(&g_cur[p * NN + dst], 1);
    g_csr[(size_t)p * NE + pos] = src;
}

// ===== CSR aggregation: one WARP per dst, two-phase softmax, fp16 h gather =====
// lane covers cols lane*8 .. lane*8+7 (head = lane>>2): one uint4 (8 halves) per edge.
__global__ void __launch_bounds__(256) agg_csr() {
    int p = blockIdx.y;
    int wid = threadIdx.x >> 5, lane = threadIdx.x & 31;
    int dst = blockIdx.x * 8 + wid;
    if (dst >= NN) return;
    __shared__ float s_w[8][NH][33];
    __shared__ int   s_src[8][32];

    int nd = p * NN + dst;
    int beg = g_off[nd], deg = g_cnt[nd];
    int head = lane >> 2;

    float4 er0 = *(const float4*)(g_er + (size_t)nd * NH);
    float4 er1 = *(const float4*)(g_er + (size_t)nd * NH + 4);
    float erv[8] = {er0.x, er0.y, er0.z, er0.w, er1.x, er1.y, er1.z, er1.w};

    float a[8];
    #pragma unroll
    for (int j = 0; j < 8; j++) a[j] = 0.f;
    float s = 0.f;
    const int* csr = g_csr + (size_t)p * NE + beg;
    const __half* hbase = g_h + (size_t)p * NN * HO;

    for (int c0 = 0; c0 < deg; c0 += 32) {
        int csz = min(32, deg - c0);
        if (lane < csz) {
            int src = csr[c0 + lane];
            s_src[wid][lane] = src;
            const float* el = g_el + ((size_t)p * NN + src) * NH;
            float4 e0 = *(const float4*)el;
            float4 e1 = *(const float4*)(el + 4);
            float elv[8] = {e0.x, e0.y, e0.z, e0.w, e1.x, e1.y, e1.z, e1.w};
            #pragma unroll
            for (int j = 0; j < 8; j++) {
                float x = elv[j] + erv[j];
                x = x > 0.f ? x : 0.2f * x;
                s_w[wid][j][lane] = __expf(fminf(x, 60.f));
            }
        }
        __syncwarp();
        int k = 0;
        for (; k + 2 <= csz; k += 2) {
            int s0 = s_src[wid][k], s1 = s_src[wid][k + 1];
            float w0 = s_w[wid][head][k], w1 = s_w[wid][head][k + 1];
            uint4 r0 = ((const uint4*)(hbase + (size_t)s0 * HO))[lane];
            uint4 r1 = ((const uint4*)(hbase + (size_t)s1 * HO))[lane];
            s += w0 + w1;
            const half2* h0 = (const half2*)&r0;
            const half2* h1 = (const half2*)&r1;
            #pragma unroll
            for (int j = 0; j < 4; j++) {
                float2 f0 = __half22float2(h0[j]);
                float2 f1 = __half22float2(h1[j]);
                a[2 * j]     += w0 * f0.x + w1 * f1.x;
                a[2 * j + 1] += w0 * f0.y + w1 * f1.y;
            }
        }
        if (k < csz) {
            int s0 = s_src[wid][k];
            float w0 = s_w[wid][head][k];
            uint4 r0 = ((const uint4*)(hbase + (size_t)s0 * HO))[lane];
            s += w0;
            const half2* h0 = (const half2*)&r0;
            #pragma unroll
            for (int j = 0; j < 4; j++) {
                float2 f0 = __half22float2(h0[j]);
                a[2 * j]     += w0 * f0.x;
                a[2 * j + 1] += w0 * f0.y;
            }
        }
        __syncwarp();
    }

    float r = (s > 0.f) ? 1.0f / s : 0.f;
    #pragma unroll
    for (int j = 0; j < 8; j++) a[j] *= r;
    float4* orow = (float4*)(g_out + (size_t)nd * HO) + lane * 2;
    orow[0] = make_float4(a[0], a[1], a[2], a[3]);
    orow[1] = make_float4(a[4], a[5], a[6], a[7]);
}

// ===== semantic: wsum[p] += sum_n tanh(elu(out+bias) @ W1 + b1) . w2  (tf32) =====
constexpr int BS2_STR = 136;  // 32 x 136 u32

__global__ void __launch_bounds__(256) sem_kernel(const float* __restrict__ bias,
                                                  const float* __restrict__ W1,
                                                  const float* __restrict__ b1,
                                                  const float* __restrict__ w2) {
    int p = blockIdx.y;
    int row0 = blockIdx.x * 64;
    __shared__ uint32_t As[64 * AS_STR];
    __shared__ uint32_t Bs[32 * BS2_STR];
    __shared__ float bsum;

    int tid = threadIdx.x, lane = tid & 31, warp = tid >> 5;
    int warpm = warp & 1, warpn = warp >> 1;  // 2 x 4
    int gid = lane >> 2, tig = lane & 3;
    const float* zb = g_out + (size_t)p * NN * HO;
    const float* bp = bias + p * HO;
    if (tid == 0) bsum = 0.f;

    float c[2][4][4];
    #pragma unroll
    for (int mt = 0; mt < 2; mt++)
        #pragma unroll
        for (int nt = 0; nt < 4; nt++)
            #pragma unroll
            for (int r = 0; r < 4; r++) c[mt][nt][r] = 0.f;

    for (int kb = 0; kb < 8; kb++) {
        #pragma unroll
        for (int it = 0; it < 2; it++) {
            int idx = tid + it * 256;
            int r = idx >> 3, c4 = idx & 7;
            int gr = row0 + r;
            float4 v = make_float4(0.f, 0.f, 0.f, 0.f);
            if (gr < NN) {
                v = *(const float4*)(zb + (size_t)gr * HO + kb * 32 + c4 * 4);
                const float* bb = bp + kb * 32 + c4 * 4;
                v.x = elu_f(v.x + bb[0]);
                v.y = elu_f(v.y + bb[1]);
                v.z = elu_f(v.z + bb[2]);
                v.w = elu_f(v.w + bb[3]);
            }
            uint4 u = make_uint4(to_tf32(v.x), to_tf32(v.y), to_tf32(v.z), to_tf32(v.w));
            *(uint4*)(As + r * AS_STR + c4 * 4) = u;
        }
        #pragma unroll
        for (int it = 0; it < 4; it++) {
            int idx = tid + it * 256;
            int k = idx >> 5, c4 = idx & 31;
            float4 v = *(const float4*)(W1 + (size_t)(kb * 32 + k) * HID + c4 * 4);
            uint4 u = make_uint4(to_tf32(v.x), to_tf32(v.y), to_tf32(v.z), to_tf32(v.w));
            *(uint4*)(Bs + k * BS2_STR + c4 * 4) = u;
        }
        __syncthreads();
        #pragma unroll
        for (int ks = 0; ks < 4; ks++) {
            int k0 = ks * 8;
            uint32_t a[2][4];
            #pragma unroll
            for (int mt = 0; mt < 2; mt++) {
                int rb = warpm * 32 + mt * 16;
                a[mt][0] = As[(rb + gid) * AS_STR + k0 + tig];
                a[mt][1] = As[(rb + gid + 8) * AS_STR + k0 + tig];
                a[mt][2] = As[(rb + gid) * AS_STR + k0 + tig + 4];
                a[mt][3] = As[(rb + gid + 8) * AS_STR + k0 + tig + 4];
            }
            #pragma unroll
            for (int nt = 0; nt < 4; nt++) {
                int n0 = warpn * 32 + nt * 8;
                uint32_t b0 = Bs[(k0 + tig) * BS2_STR + n0 + gid];
                uint32_t b1 = Bs[(k0 + tig + 4) * BS2_STR + n0 + gid];
                mma_tf32(c[0][nt], a[0], b0, b1);
                mma_tf32(c[1][nt], a[1], b0, b1);
            }
        }
        __syncthreads();
    }

    float part = 0.f;
    #pragma unroll
    for (int mt = 0; mt < 2; mt++) {
        int rb = row0 + warpm * 32 + mt * 16;
        bool ok0 = (rb + gid) < NN, ok1 = (rb + gid + 8) < NN;
        #pragma unroll
        for (int nt = 0; nt < 4; nt++) {
            int col0 = warpn * 32 + nt * 8 + 2 * tig;
            float b1a = b1[col0], b1b = b1[col0 + 1];
            float w2a = w2[col0], w2b = w2[col0 + 1];
            if (ok0) part += tanh_fast(c[mt][nt][0] + b1a) * w2a +
                             tanh_fast(c[mt][nt][1] + b1b) * w2b;
            if (ok1) part += tanh_fast(c[mt][nt][2] + b1a) * w2a +
                             tanh_fast(c[mt][nt][3] + b1b) * w2b;
        }
    }
    #pragma unroll
    for (int off = 16; off; off >>= 1)
        part += __shfl_xor_sync(0xffffffffu, part, off);
    __syncthreads();
    if (lane == 0) atomicAdd(&bsum, part);
    __syncthreads();
    if (tid == 0) atomicAdd(&g_wsum[p], bsum);
}

__global__ void beta_kernel() {
    if (threadIdx.x == 0) {
        float w0 = g_wsum[0] / NN, w1 = g_wsum[1] / NN, w2v = g_wsum[2] / NN;
        float mx = fmaxf(w0, fmaxf(w1, w2v));
        float e0 = __expf(w0 - mx), e1 = __expf(w1 - mx), e2 = __expf(w2v - mx);
        float s = e0 + e1 + e2;
        g_beta[0] = e0 / s;
        g_beta[1] = e1 / s;
        g_beta[2] = e2 / s;
    }
}

__global__ void final_kernel(const float* __restrict__ bias, float* __restrict__ dout) {
    size_t i = (size_t)blockIdx.x * blockDim.x + threadIdx.x;  // float4 index
    size_t total = (size_t)NN * HO / 4;
    if (i >= total) return;
    int c4 = (int)(i & 63);
    float bw[3] = {g_beta[0], g_beta[1], g_beta[2]};
    float4 r = make_float4(0.f, 0.f, 0.f, 0.f);
    #pragma unroll
    for (int p = 0; p < NP; p++) {
        float4 o = ((const float4*)g_out)[(size_t)p * NN * HO / 4 + i];
        const float* bp = bias + p * HO + c4 * 4;
        r.x += bw[p] * elu_f(o.x + bp[0]);
        r.y += bw[p] * elu_f(o.y + bp[1]);
        r.z += bw[p] * elu_f(o.z + bp[2]);
        r.w += bw[p] * elu_f(o.w + bp[3]);
    }
    ((float4*)dout)[i] = r;
}

// ---------------- launch ----------------
extern "C" void kernel_launch(void* const* d_in, const int* in_sizes, int n_in,
                              void* d_out, int out_size) {
    const float* feat  = (const float*)d_in[0];
    const void*  edges = d_in[1];
    const float* Ws    = (const float*)d_in[2];
    const float* al    = (const float*)d_in[3];
    const float* ar    = (const float*)d_in[4];
    const float* bias  = (const float*)d_in[5];
    const float* W1    = (const float*)d_in[6];
    const float* b1    = (const float*)d_in[7];
    const float* w2    = (const float*)d_in[8];
    float* outp = (float*)d_out;

    detect_kernel<<<1, 32>>>((const int*)edges);
    init_small<<<(NP * NN + 255) / 256, 256>>>();

    dim3 gh((NN + 63) / 64, NP);
    gemm_h<<<gh, 256>>>(feat, Ws, al, ar);

    dim3 ge((NE + 255) / 256, NP);
    hist_kernel<<<ge, 256>>>(edges);
    scan_kernel<<<NP, 1024>>>();
    scatter_kernel<<<ge, 256>>>(edges);

    agg_csr<<<dim3((NN + 7) / 8, NP), 256>>>();

    sem_kernel<<<gh, 256>>>(bias, W1, b1, w2);
    beta_kernel<<<1, 32>>>();

    final_kernel<<<(int)(((size_t)NN * HO / 4 + 255) / 256), 256>>>(bias, outp);
}

// round 14
// speedup vs baseline: 3.4839x; 1.1642x over previous
#include <cuda_runtime.h>
#include <cuda_fp16.h>
#include <math.h>
#include <stdint.h>

// Problem constants
constexpr int NN  = 50000;   // nodes
constexpr int DIN = 128;     // input feature dim
constexpr int HO  = 256;     // H*O
constexpr int NH  = 8;       // heads
constexpr int NE  = 400000;  // edges per path
constexpr int NP  = 3;       // metapaths
constexpr int HID = 128;     // semantic hidden

// ---------------- scratch (static device globals; no allocation) ----------------
__device__ __half g_h [(size_t)NP * NN * HO];   // per-path projected features (fp16)
__device__ __half g_z [(size_t)NP * NN * HO];   // per-path z = elu(out+bias) (fp16)
__device__ float g_el [NP * NN * NH];
__device__ float g_er [NP * NN * NH];
__device__ int   g_cnt[NP * NN];                // in-degree per dst
__device__ int   g_off[NP * NN];                // CSR exclusive offsets
__device__ int   g_cur[NP * NN];                // scatter cursors
__device__ int   g_csr[(size_t)NP * NE];        // src node per CSR slot
__device__ __half g_wcsr[(size_t)NP * NE * NH]; // per-slot softmax weights (8 heads, fp16)
__device__ float g_wsum[NP];
__device__ float g_beta[NP];
__device__ int   g_is64;

// ---------------- helpers ----------------
__device__ __forceinline__ float elu_f(float x) { return x > 0.f ? x : expm1f(x); }

__device__ __forceinline__ float tanh_fast(float x) {
    float y;
    asm("tanh.approx.f32 %0, %1;" : "=f"(y) : "f"(x));
    return y;
}

__device__ __forceinline__ uint32_t to_tf32(float x) {
    uint32_t r;
    asm("cvt.rna.tf32.f32 %0, %1;" : "=r"(r) : "f"(x));
    return r;
}

// D += A(16x8) * B(8x8), tf32 in, f32 accumulate
__device__ __forceinline__ void mma_tf32(float* c, const uint32_t* a,
                                         uint32_t b0, uint32_t b1) {
    asm volatile(
        "mma.sync.aligned.m16n8k8.row.col.f32.tf32.tf32.f32 "
        "{%0,%1,%2,%3}, {%4,%5,%6,%7}, {%8,%9}, {%0,%1,%2,%3};\n"
        : "+f"(c[0]), "+f"(c[1]), "+f"(c[2]), "+f"(c[3])
        : "r"(a[0]), "r"(a[1]), "r"(a[2]), "r"(a[3]), "r"(b0), "r"(b1));
}

// edges may be int64 (jax x64) or int32 (x64 disabled) — uniform device branch
__device__ __forceinline__ int edge_val(const void* edges, size_t idx) {
    if (g_is64) return (int)(((const long long*)edges)[idx]);
    return ((const int*)edges)[idx];
}

// ---------------- kernels ----------------
__global__ void detect_kernel(const int* e32) {
    if (threadIdx.x == 0 && blockIdx.x == 0) {
        int is64 = 1;
        #pragma unroll
        for (int k = 0; k < 16; k++)
            if (e32[2 * k + 1] != 0) is64 = 0;
        g_is64 = is64;
    }
}

// zero counters / cursors / wsum
__global__ void init_small() {
    int i = blockIdx.x * blockDim.x + threadIdx.x;
    if (i < NP * NN) {
        g_cnt[i] = 0;
        g_cur[i] = 0;
    }
    if (i < NP) g_wsum[i] = 0.f;
}

// ===== h_p = feat @ W_p  (tf32 tensor cores), h stored as fp16 =====
constexpr int AS_STR = 36;    // 64 x 36 u32
constexpr int BS_STR = 264;   // 32 x 264 u32

__global__ void __launch_bounds__(256) gemm_h(const float* __restrict__ feat,
                                              const float* __restrict__ Ws,
                                              const float* __restrict__ al,
                                              const float* __restrict__ ar) {
    int p = blockIdx.y;
    int row0 = blockIdx.x * 64;
    const float* W = Ws + (size_t)p * DIN * HO;
    __shared__ uint32_t As[64 * AS_STR];
    __shared__ uint32_t Bs[32 * BS_STR];
    __shared__ float al_s[HO], ar_s[HO];

    int tid = threadIdx.x, lane = tid & 31, warp = tid >> 5;
    int warpm = warp & 1, warpn = warp >> 1;  // 2 x 4
    int gid = lane >> 2, tig = lane & 3;

    al_s[tid] = al[p * HO + tid];
    ar_s[tid] = ar[p * HO + tid];

    float c[2][8][4];
    #pragma unroll
    for (int mt = 0; mt < 2; mt++)
        #pragma unroll
        for (int nt = 0; nt < 8; nt++)
            #pragma unroll
            for (int r = 0; r < 4; r++) c[mt][nt][r] = 0.f;

    for (int kb = 0; kb < 4; kb++) {
        #pragma unroll
        for (int it = 0; it < 2; it++) {
            int idx = tid + it * 256;
            int r = idx >> 3, c4 = idx & 7;
            int gr = row0 + r;
            float4 v = make_float4(0.f, 0.f, 0.f, 0.f);
            if (gr < NN) v = *(const float4*)(feat + (size_t)gr * DIN + kb * 32 + c4 * 4);
            uint4 u = make_uint4(to_tf32(v.x), to_tf32(v.y), to_tf32(v.z), to_tf32(v.w));
            *(uint4*)(As + r * AS_STR + c4 * 4) = u;
        }
        #pragma unroll
        for (int it = 0; it < 8; it++) {
            int idx = tid + it * 256;
            int k = idx >> 6, c4 = idx & 63;
            float4 v = *(const float4*)(W + (size_t)(kb * 32 + k) * HO + c4 * 4);
            uint4 u = make_uint4(to_tf32(v.x), to_tf32(v.y), to_tf32(v.z), to_tf32(v.w));
            *(uint4*)(Bs + k * BS_STR + c4 * 4) = u;
        }
        __syncthreads();
        #pragma unroll
        for (int ks = 0; ks < 4; ks++) {
            int k0 = ks * 8;
            uint32_t a[2][4];
            #pragma unroll
            for (int mt = 0; mt < 2; mt++) {
                int rb = warpm * 32 + mt * 16;
                a[mt][0] = As[(rb + gid) * AS_STR + k0 + tig];
                a[mt][1] = As[(rb + gid + 8) * AS_STR + k0 + tig];
                a[mt][2] = As[(rb + gid) * AS_STR + k0 + tig + 4];
                a[mt][3] = As[(rb + gid + 8) * AS_STR + k0 + tig + 4];
            }
            #pragma unroll
            for (int nt = 0; nt < 8; nt++) {
                int n0 = warpn * 64 + nt * 8;
                uint32_t b0 = Bs[(k0 + tig) * BS_STR + n0 + gid];
                uint32_t b1 = Bs[(k0 + tig + 4) * BS_STR + n0 + gid];
                mma_tf32(c[0][nt], a[0], b0, b1);
                mma_tf32(c[1][nt], a[1], b0, b1);
            }
        }
        __syncthreads();
    }

    // epilogue: store h (fp16), fused el/er (warp covers heads warpn*2, warpn*2+1)
    int node[2][2];
    #pragma unroll
    for (int mt = 0; mt < 2; mt++) {
        node[mt][0] = row0 + warpm * 32 + mt * 16 + gid;
        node[mt][1] = node[mt][0] + 8;
    }
    float pl[2][2][2], pr[2][2][2];
    #pragma unroll
    for (int mt = 0; mt < 2; mt++)
        #pragma unroll
        for (int rh = 0; rh < 2; rh++)
            #pragma unroll
            for (int hl = 0; hl < 2; hl++) { pl[mt][rh][hl] = 0.f; pr[mt][rh][hl] = 0.f; }

    #pragma unroll
    for (int nt = 0; nt < 8; nt++) {
        int col0 = warpn * 64 + nt * 8 + 2 * tig;
        int hl = nt >> 2;
        float a0l = al_s[col0], a1l = al_s[col0 + 1];
        float a0r = ar_s[col0], a1r = ar_s[col0 + 1];
        #pragma unroll
        for (int mt = 0; mt < 2; mt++) {
            float v0 = c[mt][nt][0], v1 = c[mt][nt][1];
            float v2 = c[mt][nt][2], v3 = c[mt][nt][3];
            pl[mt][0][hl] += v0 * a0l + v1 * a1l;
            pr[mt][0][hl] += v0 * a0r + v1 * a1r;
            pl[mt][1][hl] += v2 * a0l + v3 * a1l;
            pr[mt][1][hl] += v2 * a0r + v3 * a1r;
            if (node[mt][0] < NN)
                *(half2*)(g_h + ((size_t)p * NN + node[mt][0]) * HO + col0) =
                    __floats2half2_rn(v0, v1);
            if (node[mt][1] < NN)
                *(half2*)(g_h + ((size_t)p * NN + node[mt][1]) * HO + col0) =
                    __floats2half2_rn(v2, v3);
        }
    }
    #pragma unroll
    for (int off = 1; off <= 2; off <<= 1)
        #pragma unroll
        for (int mt = 0; mt < 2; mt++)
            #pragma unroll
            for (int rh = 0; rh < 2; rh++)
                #pragma unroll
                for (int hl = 0; hl < 2; hl++) {
                    pl[mt][rh][hl] += __shfl_xor_sync(0xffffffffu, pl[mt][rh][hl], off);
                    pr[mt][rh][hl] += __shfl_xor_sync(0xffffffffu, pr[mt][rh][hl], off);
                }
    if (tig == 0) {
        #pragma unroll
        for (int mt = 0; mt < 2; mt++)
            #pragma unroll
            for (int rh = 0; rh < 2; rh++) {
                int nd = node[mt][rh];
                if (nd < NN) {
                    *(float2*)(g_el + ((size_t)p * NN + nd) * NH + warpn * 2) =
                        make_float2(pl[mt][rh][0], pl[mt][rh][1]);
                    *(float2*)(g_er + ((size_t)p * NN + nd) * NH + warpn * 2) =
                        make_float2(pr[mt][rh][0], pr[mt][rh][1]);
                }
            }
    }
}

// CSR build: histogram of dst
__global__ void hist_kernel(const void* __restrict__ edges) {
    int p = blockIdx.y;
    int e = blockIdx.x * blockDim.x + threadIdx.x;
    if (e >= NE) return;
    int dst = edge_val(edges, (size_t)2 * p * NE + NE + e);
    atomicAdd(&g_cnt[p * NN + dst], 1);
}

// exclusive prefix sum over counts, one block (1024 thr) per path
__global__ void __launch_bounds__(1024) scan_kernel() {
    __shared__ int wsum[32];
    __shared__ int carry;
    int p = blockIdx.x;
    int tid = threadIdx.x, lane = tid & 31, wid = tid >> 5;
    if (tid == 0) carry = 0;
    __syncthreads();
    for (int base = 0; base < NN; base += 1024) {
        int i = base + tid;
        int v = (i < NN) ? g_cnt[p * NN + i] : 0;
        int x = v;
        #pragma unroll
        for (int o = 1; o < 32; o <<= 1) {
            int y = __shfl_up_sync(0xffffffffu, x, o);
            if (lane >= o) x += y;
        }
        if (lane == 31) wsum[wid] = x;
        __syncthreads();
        if (wid == 0) {
            int w = wsum[lane];
            #pragma unroll
            for (int o = 1; o < 32; o <<= 1) {
                int y = __shfl_up_sync(0xffffffffu, w, o);
                if (lane >= o) w += y;
            }
            wsum[lane] = w;
        }
        __syncthreads();
        int warp_off = (wid == 0) ? 0 : wsum[wid - 1];
        if (i < NN) g_off[p * NN + i] = carry + warp_off + x - v;
        int total = wsum[31];
        __syncthreads();
        if (tid == 0) carry += total;
        __syncthreads();
    }
}

// scatter src ids into CSR slots AND compute per-edge softmax weights (8 heads, fp16)
__global__ void scatter_kernel(const void* __restrict__ edges) {
    int p = blockIdx.y;
    int e = blockIdx.x * blockDim.x + threadIdx.x;
    if (e >= NE) return;
    size_t base = (size_t)2 * p * NE;
    int src = edge_val(edges, base + e);
    int dst = edge_val(edges, base + NE + e);
    int nd = p * NN + dst;
    int pos = g_off[nd] + atomicAdd(&g_cur[nd], 1);
    size_t slot = (size_t)p * NE + pos;
    g_csr[slot] = src;

    const float* el = g_el + ((size_t)p * NN + src) * NH;
    const float* er = g_er + (size_t)nd * NH;
    float4 e0 = *(const float4*)el;
    float4 e1 = *(const float4*)(el + 4);
    float4 r0 = *(const float4*)er;
    float4 r1 = *(const float4*)(er + 4);
    float xv[8] = {e0.x + r0.x, e0.y + r0.y, e0.z + r0.z, e0.w + r0.w,
                   e1.x + r1.x, e1.y + r1.y, e1.z + r1.z, e1.w + r1.w};
    half2 wv[4];
    #pragma unroll
    for (int j = 0; j < 4; j++) {
        float xa = xv[2 * j],     wa;
        float xb = xv[2 * j + 1], wb;
        xa = xa > 0.f ? xa : 0.2f * xa;
        xb = xb > 0.f ? xb : 0.2f * xb;
        wa = __expf(fminf(xa, 10.f));
        wb = __expf(fminf(xb, 10.f));
        wv[j] = __floats2half2_rn(wa, wb);
    }
    *(uint4*)(g_wcsr + slot * NH) = *(uint4*)wv;
}

// ===== CSR aggregation: one WARP per dst; w precomputed (CSR-ordered fp16) =====
// lane covers cols lane*8 .. lane*8+7 (head = lane>>2): one uint4 (8 halves) per edge.
// Epilogue stores z = elu(out + bias) as fp16.
__global__ void __launch_bounds__(256) agg_csr(const float* __restrict__ bias) {
    int p = blockIdx.y;
    int wid = threadIdx.x >> 5, lane = threadIdx.x & 31;
    int dst = blockIdx.x * 8 + wid;
    if (dst >= NN) return;
    __shared__ float s_w[8][NH][33];
    __shared__ int   s_src[8][32];

    int nd = p * NN + dst;
    int beg = g_off[nd], deg = g_cnt[nd];
    int head = lane >> 2;

    float a[8];
    #pragma unroll
    for (int j = 0; j < 8; j++) a[j] = 0.f;
    float s = 0.f;
    const int* csr = g_csr + (size_t)p * NE + beg;
    const uint4* wcsr = (const uint4*)(g_wcsr + ((size_t)p * NE + beg) * NH);
    const __half* hbase = g_h + (size_t)p * NN * HO;

    for (int c0 = 0; c0 < deg; c0 += 32) {
        int csz = min(32, deg - c0);
        if (lane < csz) {
            s_src[wid][lane] = csr[c0 + lane];
            uint4 wv = wcsr[c0 + lane];
            const half2* wh = (const half2*)&wv;
            #pragma unroll
            for (int j = 0; j < 4; j++) {
                float2 f = __half22float2(wh[j]);
                s_w[wid][2 * j][lane]     = f.x;
                s_w[wid][2 * j + 1][lane] = f.y;
            }
        }
        __syncwarp();
        int k = 0;
        for (; k + 2 <= csz; k += 2) {
            int s0 = s_src[wid][k], s1 = s_src[wid][k + 1];
            float w0 = s_w[wid][head][k], w1 = s_w[wid][head][k + 1];
            uint4 r0 = ((const uint4*)(hbase + (size_t)s0 * HO))[lane];
            uint4 r1 = ((const uint4*)(hbase + (size_t)s1 * HO))[lane];
            s += w0 + w1;
            const half2* h0 = (const half2*)&r0;
            const half2* h1 = (const half2*)&r1;
            #pragma unroll
            for (int j = 0; j < 4; j++) {
                float2 f0 = __half22float2(h0[j]);
                float2 f1 = __half22float2(h1[j]);
                a[2 * j]     += w0 * f0.x + w1 * f1.x;
                a[2 * j + 1] += w0 * f0.y + w1 * f1.y;
            }
        }
        if (k < csz) {
            int s0 = s_src[wid][k];
            float w0 = s_w[wid][head][k];
            uint4 r0 = ((const uint4*)(hbase + (size_t)s0 * HO))[lane];
            s += w0;
            const half2* h0 = (const half2*)&r0;
            #pragma unroll
            for (int j = 0; j < 4; j++) {
                float2 f0 = __half22float2(h0[j]);
                a[2 * j]     += w0 * f0.x;
                a[2 * j + 1] += w0 * f0.y;
            }
        }
        __syncwarp();
    }

    float r = (s > 0.f) ? 1.0f / s : 0.f;
    const float* bp = bias + p * HO + lane * 8;
    float4 b0 = *(const float4*)bp;
    float4 b1 = *(const float4*)(bp + 4);
    float bb[8] = {b0.x, b0.y, b0.z, b0.w, b1.x, b1.y, b1.z, b1.w};
    half2 zv[4];
    #pragma unroll
    for (int j = 0; j < 4; j++) {
        float za = elu_f(a[2 * j] * r + bb[2 * j]);
        float zb = elu_f(a[2 * j + 1] * r + bb[2 * j + 1]);
        zv[j] = __floats2half2_rn(za, zb);
    }
    *(uint4*)(g_z + (size_t)nd * HO + lane * 8) = *(uint4*)zv;
}

// ===== semantic: wsum[p] += sum_n tanh(z @ W1 + b1) . w2  (tf32, z fp16) =====
constexpr int BS2_STR = 136;  // 32 x 136 u32

__global__ void __launch_bounds__(256) sem_kernel(const float* __restrict__ W1,
                                                  const float* __restrict__ b1,
                                                  const float* __restrict__ w2) {
    int p = blockIdx.y;
    int row0 = blockIdx.x * 64;
    __shared__ uint32_t As[64 * AS_STR];
    __shared__ uint32_t Bs[32 * BS2_STR];
    __shared__ float bsum;

    int tid = threadIdx.x, lane = tid & 31, warp = tid >> 5;
    int warpm = warp & 1, warpn = warp >> 1;  // 2 x 4
    int gid = lane >> 2, tig = lane & 3;
    const __half* zb = g_z + (size_t)p * NN * HO;
    if (tid == 0) bsum = 0.f;

    float c[2][4][4];
    #pragma unroll
    for (int mt = 0; mt < 2; mt++)
        #pragma unroll
        for (int nt = 0; nt < 4; nt++)
            #pragma unroll
            for (int r = 0; r < 4; r++) c[mt][nt][r] = 0.f;

    for (int kb = 0; kb < 8; kb++) {
        // A tile 64x32 fp16: 256 uint4 (8 halves each), one per thread
        {
            int r = tid >> 2, c8 = tid & 3;
            int gr = row0 + r;
            uint4 v = make_uint4(0u, 0u, 0u, 0u);
            if (gr < NN) v = *(const uint4*)(zb + (size_t)gr * HO + kb * 32 + c8 * 8);
            const half2* h = (const half2*)&v;
            uint32_t o[8];
            #pragma unroll
            for (int j = 0; j < 4; j++) {
                float2 f = __half22float2(h[j]);
                o[2 * j]     = to_tf32(f.x);
                o[2 * j + 1] = to_tf32(f.y);
            }
            *(uint4*)(As + r * AS_STR + c8 * 8)     = *(uint4*)(o);
            *(uint4*)(As + r * AS_STR + c8 * 8 + 4) = *(uint4*)(o + 4);
        }
        #pragma unroll
        for (int it = 0; it < 4; it++) {
            int idx = tid + it * 256;
            int k = idx >> 5, c4 = idx & 31;
            float4 v = *(const float4*)(W1 + (size_t)(kb * 32 + k) * HID + c4 * 4);
            uint4 u = make_uint4(to_tf32(v.x), to_tf32(v.y), to_tf32(v.z), to_tf32(v.w));
            *(uint4*)(Bs + k * BS2_STR + c4 * 4) = u;
        }
        __syncthreads();
        #pragma unroll
        for (int ks = 0; ks < 4; ks++) {
            int k0 = ks * 8;
            uint32_t a[2][4];
            #pragma unroll
            for (int mt = 0; mt < 2; mt++) {
                int rb = warpm * 32 + mt * 16;
                a[mt][0] = As[(rb + gid) * AS_STR + k0 + tig];
                a[mt][1] = As[(rb + gid + 8) * AS_STR + k0 + tig];
                a[mt][2] = As[(rb + gid) * AS_STR + k0 + tig + 4];
                a[mt][3] = As[(rb + gid + 8) * AS_STR + k0 + tig + 4];
            }
            #pragma unroll
            for (int nt = 0; nt < 4; nt++) {
                int n0 = warpn * 32 + nt * 8;
                uint32_t b0 = Bs[(k0 + tig) * BS2_STR + n0 + gid];
                uint32_t b1 = Bs[(k0 + tig + 4) * BS2_STR + n0 + gid];
                mma_tf32(c[0][nt], a[0], b0, b1);
                mma_tf32(c[1][nt], a[1], b0, b1);
            }
        }
        __syncthreads();
    }

    float part = 0.f;
    #pragma unroll
    for (int mt = 0; mt < 2; mt++) {
        int rb = row0 + warpm * 32 + mt * 16;
        bool ok0 = (rb + gid) < NN, ok1 = (rb + gid + 8) < NN;
        #pragma unroll
        for (int nt = 0; nt < 4; nt++) {
            int col0 = warpn * 32 + nt * 8 + 2 * tig;
            float b1a = b1[col0], b1b = b1[col0 + 1];
            float w2a = w2[col0], w2b = w2[col0 + 1];
            if (ok0) part += tanh_fast(c[mt][nt][0] + b1a) * w2a +
                             tanh_fast(c[mt][nt][1] + b1b) * w2b;
            if (ok1) part += tanh_fast(c[mt][nt][2] + b1a) * w2a +
                             tanh_fast(c[mt][nt][3] + b1b) * w2b;
        }
    }
    #pragma unroll
    for (int off = 16; off; off >>= 1)
        part += __shfl_xor_sync(0xffffffffu, part, off);
    __syncthreads();
    if (lane == 0) atomicAdd(&bsum, part);
    __syncthreads();
    if (tid == 0) atomicAdd(&g_wsum[p], bsum);
}

__global__ void beta_kernel() {
    if (threadIdx.x == 0) {
        float w0 = g_wsum[0] / NN, w1 = g_wsum[1] / NN, w2v = g_wsum[2] / NN;
        float mx = fmaxf(w0, fmaxf(w1, w2v));
        float e0 = __expf(w0 - mx), e1 = __expf(w1 - mx), e2 = __expf(w2v - mx);
        float s = e0 + e1 + e2;
        g_beta[0] = e0 / s;
        g_beta[1] = e1 / s;
        g_beta[2] = e2 / s;
    }
}

// out = sum_p beta[p] * z_p  (z fp16, output fp32)
__global__ void final_kernel(float* __restrict__ dout) {
    size_t i = (size_t)blockIdx.x * blockDim.x + threadIdx.x;  // uint4 index (8 halves)
    size_t total = (size_t)NN * HO / 8;
    if (i >= total) return;
    float bw[3] = {g_beta[0], g_beta[1], g_beta[2]};
    float r[8];
    #pragma unroll
    for (int j = 0; j < 8; j++) r[j] = 0.f;
    #pragma unroll
    for (int p = 0; p < NP; p++) {
        uint4 v = ((const uint4*)g_z)[(size_t)p * NN * HO / 8 + i];
        const half2* h = (const half2*)&v;
        #pragma unroll
        for (int j = 0; j < 4; j++) {
            float2 f = __half22float2(h[j]);
            r[2 * j]     += bw[p] * f.x;
            r[2 * j + 1] += bw[p] * f.y;
        }
    }
    float4* o = (float4*)dout + i * 2;
    o[0] = make_float4(r[0], r[1], r[2], r[3]);
    o[1] = make_float4(r[4], r[5], r[6], r[7]);
}

// ---------------- launch ----------------
extern "C" void kernel_launch(void* const* d_in, const int* in_sizes, int n_in,
                              void* d_out, int out_size) {
    const float* feat  = (const float*)d_in[0];
    const void*  edges = d_in[1];
    const float* Ws    = (const float*)d_in[2];
    const float* al    = (const float*)d_in[3];
    const float* ar    = (const float*)d_in[4];
    const float* bias  = (const float*)d_in[5];
    const float* W1    = (const float*)d_in[6];
    const float* b1    = (const float*)d_in[7];
    const float* w2    = (const float*)d_in[8];
    float* outp = (float*)d_out;

    detect_kernel<<<1, 32>>>((const int*)edges);
    init_small<<<(NP * NN + 255) / 256, 256>>>();

    dim3 gh((NN + 63) / 64, NP);
    gemm_h<<<gh, 256>>>(feat, Ws, al, ar);

    dim3 ge((NE + 255) / 256, NP);
    hist_kernel<<<ge, 256>>>(edges);
    scan_kernel<<<NP, 1024>>>();
    scatter_kernel<<<ge, 256>>>(edges);

    agg_csr<<<dim3((NN + 7) / 8, NP), 256>>>(bias);

    sem_kernel<<<gh, 256>>>(W1, b1, w2);
    beta_kernel<<<1, 32>>>();

    final_kernel<<<(int)(((size_t)NN * HO / 8 + 255) / 256), 256>>>(outp);
}

// round 15
// speedup vs baseline: 3.6999x; 1.0620x over previous
#include <cuda_runtime.h>
#include <cuda_fp16.h>
#include <math.h>
#include <stdint.h>

// Problem constants
constexpr int NN  = 50000;   // nodes
constexpr int DIN = 128;     // input feature dim
constexpr int HO  = 256;     // H*O
constexpr int NH  = 8;       // heads
constexpr int NE  = 400000;  // edges per path
constexpr int NP  = 3;       // metapaths
constexpr int HID = 128;     // semantic hidden

// ---------------- scratch (static device globals; no allocation) ----------------
__device__ __half g_h [(size_t)NP * NN * HO];   // per-path projected features (fp16)
__device__ __half g_z [(size_t)NP * NN * HO];   // per-path z = elu(out+bias) (fp16)
__device__ float g_el [NP * NN * NH];
__device__ float g_er [NP * NN * NH];
__device__ int   g_cnt[NP * NN];                // in-degree per dst
__device__ int   g_off[NP * NN];                // CSR exclusive offsets
__device__ int   g_cur[NP * NN];                // scatter cursors
__device__ int   g_csr[(size_t)NP * NE];        // src node per CSR slot
__device__ __half g_wcsr[(size_t)NP * NE * NH]; // per-slot softmax weights (8 heads, fp16)
__device__ __half g_w1t[HID * HO];              // W1 transposed [n][k], fp16
__device__ float g_wsum[NP];
__device__ float g_beta[NP];
__device__ int   g_is64;

// ---------------- helpers ----------------
__device__ __forceinline__ float elu_f(float x) { return x > 0.f ? x : expm1f(x); }

__device__ __forceinline__ float tanh_fast(float x) {
    float y;
    asm("tanh.approx.f32 %0, %1;" : "=f"(y) : "f"(x));
    return y;
}

__device__ __forceinline__ uint32_t to_tf32(float x) {
    uint32_t r;
    asm("cvt.rna.tf32.f32 %0, %1;" : "=r"(r) : "f"(x));
    return r;
}

// D += A(16x8) * B(8x8), tf32 in, f32 accumulate
__device__ __forceinline__ void mma_tf32(float* c, const uint32_t* a,
                                         uint32_t b0, uint32_t b1) {
    asm volatile(
        "mma.sync.aligned.m16n8k8.row.col.f32.tf32.tf32.f32 "
        "{%0,%1,%2,%3}, {%4,%5,%6,%7}, {%8,%9}, {%0,%1,%2,%3};\n"
        : "+f"(c[0]), "+f"(c[1]), "+f"(c[2]), "+f"(c[3])
        : "r"(a[0]), "r"(a[1]), "r"(a[2]), "r"(a[3]), "r"(b0), "r"(b1));
}

// D += A(16x16) * B(16x8), fp16 in, f32 accumulate
__device__ __forceinline__ void mma_f16(float* c, const uint32_t* a,
                                        uint32_t b0, uint32_t b1) {
    asm volatile(
        "mma.sync.aligned.m16n8k16.row.col.f32.f16.f16.f32 "
        "{%0,%1,%2,%3}, {%4,%5,%6,%7}, {%8,%9}, {%0,%1,%2,%3};\n"
        : "+f"(c[0]), "+f"(c[1]), "+f"(c[2]), "+f"(c[3])
        : "r"(a[0]), "r"(a[1]), "r"(a[2]), "r"(a[3]), "r"(b0), "r"(b1));
}

// edges may be int64 (jax x64) or int32 (x64 disabled) — uniform device branch
__device__ __forceinline__ int edge_val(const void* edges, size_t idx) {
    if (g_is64) return (int)(((const long long*)edges)[idx]);
    return ((const int*)edges)[idx];
}

// ---------------- kernels ----------------
__global__ void detect_kernel(const int* e32) {
    if (threadIdx.x == 0 && blockIdx.x == 0) {
        int is64 = 1;
        #pragma unroll
        for (int k = 0; k < 16; k++)
            if (e32[2 * k + 1] != 0) is64 = 0;
        g_is64 = is64;
    }
}

// zero counters / cursors / wsum
__global__ void init_small() {
    int i = blockIdx.x * blockDim.x + threadIdx.x;
    if (i < NP * NN) {
        g_cnt[i] = 0;
        g_cur[i] = 0;
    }
    if (i < NP) g_wsum[i] = 0.f;
}

// one-off: W1 [k=HO][n=HID] fp32 -> g_w1t [n][k] fp16
__global__ void w1t_kernel(const float* __restrict__ W1) {
    int i = blockIdx.x * blockDim.x + threadIdx.x;
    if (i >= HID * HO) return;
    int k = i >> 7, n = i & 127;          // coalesced read of W1
    g_w1t[n * HO + k] = __float2half_rn(W1[(size_t)k * HID + n]);
}

// ===== h_p = feat @ W_p  (tf32 tensor cores), h stored as fp16 =====
constexpr int AS_STR = 36;    // 64 x 36 u32
constexpr int BS_STR = 264;   // 32 x 264 u32

__global__ void __launch_bounds__(256) gemm_h(const float* __restrict__ feat,
                                              const float* __restrict__ Ws,
                                              const float* __restrict__ al,
                                              const float* __restrict__ ar) {
    int p = blockIdx.y;
    int row0 = blockIdx.x * 64;
    const float* W = Ws + (size_t)p * DIN * HO;
    __shared__ uint32_t As[64 * AS_STR];
    __shared__ uint32_t Bs[32 * BS_STR];
    __shared__ float al_s[HO], ar_s[HO];

    int tid = threadIdx.x, lane = tid & 31, warp = tid >> 5;
    int warpm = warp & 1, warpn = warp >> 1;  // 2 x 4
    int gid = lane >> 2, tig = lane & 3;

    al_s[tid] = al[p * HO + tid];
    ar_s[tid] = ar[p * HO + tid];

    float c[2][8][4];
    #pragma unroll
    for (int mt = 0; mt < 2; mt++)
        #pragma unroll
        for (int nt = 0; nt < 8; nt++)
            #pragma unroll
            for (int r = 0; r < 4; r++) c[mt][nt][r] = 0.f;

    for (int kb = 0; kb < 4; kb++) {
        #pragma unroll
        for (int it = 0; it < 2; it++) {
            int idx = tid + it * 256;
            int r = idx >> 3, c4 = idx & 7;
            int gr = row0 + r;
            float4 v = make_float4(0.f, 0.f, 0.f, 0.f);
            if (gr < NN) v = *(const float4*)(feat + (size_t)gr * DIN + kb * 32 + c4 * 4);
            uint4 u = make_uint4(to_tf32(v.x), to_tf32(v.y), to_tf32(v.z), to_tf32(v.w));
            *(uint4*)(As + r * AS_STR + c4 * 4) = u;
        }
        #pragma unroll
        for (int it = 0; it < 8; it++) {
            int idx = tid + it * 256;
            int k = idx >> 6, c4 = idx & 63;
            float4 v = *(const float4*)(W + (size_t)(kb * 32 + k) * HO + c4 * 4);
            uint4 u = make_uint4(to_tf32(v.x), to_tf32(v.y), to_tf32(v.z), to_tf32(v.w));
            *(uint4*)(Bs + k * BS_STR + c4 * 4) = u;
        }
        __syncthreads();
        #pragma unroll
        for (int ks = 0; ks < 4; ks++) {
            int k0 = ks * 8;
            uint32_t a[2][4];
            #pragma unroll
            for (int mt = 0; mt < 2; mt++) {
                int rb = warpm * 32 + mt * 16;
                a[mt][0] = As[(rb + gid) * AS_STR + k0 + tig];
                a[mt][1] = As[(rb + gid + 8) * AS_STR + k0 + tig];
                a[mt][2] = As[(rb + gid) * AS_STR + k0 + tig + 4];
                a[mt][3] = As[(rb + gid + 8) * AS_STR + k0 + tig + 4];
            }
            #pragma unroll
            for (int nt = 0; nt < 8; nt++) {
                int n0 = warpn * 64 + nt * 8;
                uint32_t b0 = Bs[(k0 + tig) * BS_STR + n0 + gid];
                uint32_t b1 = Bs[(k0 + tig + 4) * BS_STR + n0 + gid];
                mma_tf32(c[0][nt], a[0], b0, b1);
                mma_tf32(c[1][nt], a[1], b0, b1);
            }
        }
        __syncthreads();
    }

    // epilogue: store h (fp16), fused el/er (warp covers heads warpn*2, warpn*2+1)
    int node[2][2];
    #pragma unroll
    for (int mt = 0; mt < 2; mt++) {
        node[mt][0] = row0 + warpm * 32 + mt * 16 + gid;
        node[mt][1] = node[mt][0] + 8;
    }
    float pl[2][2][2], pr[2][2][2];
    #pragma unroll
    for (int mt = 0; mt < 2; mt++)
        #pragma unroll
        for (int rh = 0; rh < 2; rh++)
            #pragma unroll
            for (int hl = 0; hl < 2; hl++) { pl[mt][rh][hl] = 0.f; pr[mt][rh][hl] = 0.f; }

    #pragma unroll
    for (int nt = 0; nt < 8; nt++) {
        int col0 = warpn * 64 + nt * 8 + 2 * tig;
        int hl = nt >> 2;
        float a0l = al_s[col0], a1l = al_s[col0 + 1];
        float a0r = ar_s[col0], a1r = ar_s[col0 + 1];
        #pragma unroll
        for (int mt = 0; mt < 2; mt++) {
            float v0 = c[mt][nt][0], v1 = c[mt][nt][1];
            float v2 = c[mt][nt][2], v3 = c[mt][nt][3];
            pl[mt][0][hl] += v0 * a0l + v1 * a1l;
            pr[mt][0][hl] += v0 * a0r + v1 * a1r;
            pl[mt][1][hl] += v2 * a0l + v3 * a1l;
            pr[mt][1][hl] += v2 * a0r + v3 * a1r;
            if (node[mt][0] < NN)
                *(half2*)(g_h + ((size_t)p * NN + node[mt][0]) * HO + col0) =
                    __floats2half2_rn(v0, v1);
            if (node[mt][1] < NN)
                *(half2*)(g_h + ((size_t)p * NN + node[mt][1]) * HO + col0) =
                    __floats2half2_rn(v2, v3);
        }
    }
    #pragma unroll
    for (int off = 1; off <= 2; off <<= 1)
        #pragma unroll
        for (int mt = 0; mt < 2; mt++)
            #pragma unroll
            for (int rh = 0; rh < 2; rh++)
                #pragma unroll
                for (int hl = 0; hl < 2; hl++) {
                    pl[mt][rh][hl] += __shfl_xor_sync(0xffffffffu, pl[mt][rh][hl], off);
                    pr[mt][rh][hl] += __shfl_xor_sync(0xffffffffu, pr[mt][rh][hl], off);
                }
    if (tig == 0) {
        #pragma unroll
        for (int mt = 0; mt < 2; mt++)
            #pragma unroll
            for (int rh = 0; rh < 2; rh++) {
                int nd = node[mt][rh];
                if (nd < NN) {
                    *(float2*)(g_el + ((size_t)p * NN + nd) * NH + warpn * 2) =
                        make_float2(pl[mt][rh][0], pl[mt][rh][1]);
                    *(float2*)(g_er + ((size_t)p * NN + nd) * NH + warpn * 2) =
                        make_float2(pr[mt][rh][0], pr[mt][rh][1]);
                }
            }
    }
}

// CSR build: histogram of dst
__global__ void hist_kernel(const void* __restrict__ edges) {
    int p = blockIdx.y;
    int e = blockIdx.x * blockDim.x + threadIdx.x;
    if (e >= NE) return;
    int dst = edge_val(edges, (size_t)2 * p * NE + NE + e);
    atomicAdd(&g_cnt[p * NN + dst], 1);
}

// exclusive prefix sum over counts, one block (1024 thr) per path
__global__ void __launch_bounds__(1024) scan_kernel() {
    __shared__ int wsum[32];
    __shared__ int carry;
    int p = blockIdx.x;
    int tid = threadIdx.x, lane = tid & 31, wid = tid >> 5;
    if (tid == 0) carry = 0;
    __syncthreads();
    for (int base = 0; base < NN; base += 1024) {
        int i = base + tid;
        int v = (i < NN) ? g_cnt[p * NN + i] : 0;
        int x = v;
        #pragma unroll
        for (int o = 1; o < 32; o <<= 1) {
            int y = __shfl_up_sync(0xffffffffu, x, o);
            if (lane >= o) x += y;
        }
        if (lane == 31) wsum[wid] = x;
        __syncthreads();
        if (wid == 0) {
            int w = wsum[lane];
            #pragma unroll
            for (int o = 1; o < 32; o <<= 1) {
                int y = __shfl_up_sync(0xffffffffu, w, o);
                if (lane >= o) w += y;
            }
            wsum[lane] = w;
        }
        __syncthreads();
        int warp_off = (wid == 0) ? 0 : wsum[wid - 1];
        if (i < NN) g_off[p * NN + i] = carry + warp_off + x - v;
        int total = wsum[31];
        __syncthreads();
        if (tid == 0) carry += total;
        __syncthreads();
    }
}

// scatter src ids into CSR slots AND compute per-edge softmax weights (8 heads, fp16)
__global__ void scatter_kernel(const void* __restrict__ edges) {
    int p = blockIdx.y;
    int e = blockIdx.x * blockDim.x + threadIdx.x;
    if (e >= NE) return;
    size_t base = (size_t)2 * p * NE;
    int src = edge_val(edges, base + e);
    int dst = edge_val(edges, base + NE + e);
    int nd = p * NN + dst;
    int pos = g_off[nd] + atomicAdd(&g_cur[nd], 1);
    size_t slot = (size_t)p * NE + pos;
    g_csr[slot] = src;

    const float* el = g_el + ((size_t)p * NN + src) * NH;
    const float* er = g_er + (size_t)nd * NH;
    float4 e0 = *(const float4*)el;
    float4 e1 = *(const float4*)(el + 4);
    float4 r0 = *(const float4*)er;
    float4 r1 = *(const float4*)(er + 4);
    float xv[8] = {e0.x + r0.x, e0.y + r0.y, e0.z + r0.z, e0.w + r0.w,
                   e1.x + r1.x, e1.y + r1.y, e1.z + r1.z, e1.w + r1.w};
    half2 wv[4];
    #pragma unroll
    for (int j = 0; j < 4; j++) {
        float xa = xv[2 * j],     wa;
        float xb = xv[2 * j + 1], wb;
        xa = xa > 0.f ? xa : 0.2f * xa;
        xb = xb > 0.f ? xb : 0.2f * xb;
        wa = __expf(fminf(xa, 10.f));
        wb = __expf(fminf(xb, 10.f));
        wv[j] = __floats2half2_rn(wa, wb);
    }
    *(uint4*)(g_wcsr + slot * NH) = *(uint4*)wv;
}

// ===== CSR aggregation: one WARP per dst; w precomputed (CSR-ordered fp16) =====
// lane covers cols lane*8 .. lane*8+7 (head = lane>>2): one uint4 (8 halves) per edge.
// Gather loop unrolled by 4 for MLP. Epilogue stores z = elu(out + bias) as fp16.
__global__ void __launch_bounds__(256) agg_csr(const float* __restrict__ bias) {
    int p = blockIdx.y;
    int wid = threadIdx.x >> 5, lane = threadIdx.x & 31;
    int dst = blockIdx.x * 8 + wid;
    if (dst >= NN) return;
    __shared__ float s_w[8][NH][33];
    __shared__ int   s_src[8][32];

    int nd = p * NN + dst;
    int beg = g_off[nd], deg = g_cnt[nd];
    int head = lane >> 2;

    float a[8];
    #pragma unroll
    for (int j = 0; j < 8; j++) a[j] = 0.f;
    float s = 0.f;
    const int* csr = g_csr + (size_t)p * NE + beg;
    const uint4* wcsr = (const uint4*)(g_wcsr + ((size_t)p * NE + beg) * NH);
    const __half* hbase = g_h + (size_t)p * NN * HO;

    for (int c0 = 0; c0 < deg; c0 += 32) {
        int csz = min(32, deg - c0);
        if (lane < csz) {
            s_src[wid][lane] = csr[c0 + lane];
            uint4 wv = wcsr[c0 + lane];
            const half2* wh = (const half2*)&wv;
            #pragma unroll
            for (int j = 0; j < 4; j++) {
                float2 f = __half22float2(wh[j]);
                s_w[wid][2 * j][lane]     = f.x;
                s_w[wid][2 * j + 1][lane] = f.y;
            }
        }
        __syncwarp();
        int k = 0;
        for (; k + 4 <= csz; k += 4) {
            int s0 = s_src[wid][k],     s1 = s_src[wid][k + 1];
            int s2 = s_src[wid][k + 2], s3 = s_src[wid][k + 3];
            float w0 = s_w[wid][head][k],     w1 = s_w[wid][head][k + 1];
            float w2 = s_w[wid][head][k + 2], w3 = s_w[wid][head][k + 3];
            uint4 r0 = ((const uint4*)(hbase + (size_t)s0 * HO))[lane];
            uint4 r1 = ((const uint4*)(hbase + (size_t)s1 * HO))[lane];
            uint4 r2 = ((const uint4*)(hbase + (size_t)s2 * HO))[lane];
            uint4 r3 = ((const uint4*)(hbase + (size_t)s3 * HO))[lane];
            s += (w0 + w1) + (w2 + w3);
            const half2* h0 = (const half2*)&r0;
            const half2* h1 = (const half2*)&r1;
            const half2* h2 = (const half2*)&r2;
            const half2* h3 = (const half2*)&r3;
            #pragma unroll
            for (int j = 0; j < 4; j++) {
                float2 f0 = __half22float2(h0[j]);
                float2 f1 = __half22float2(h1[j]);
                float2 f2 = __half22float2(h2[j]);
                float2 f3 = __half22float2(h3[j]);
                a[2 * j]     += (w0 * f0.x + w1 * f1.x) + (w2 * f2.x + w3 * f3.x);
                a[2 * j + 1] += (w0 * f0.y + w1 * f1.y) + (w2 * f2.y + w3 * f3.y);
            }
        }
        for (; k < csz; k++) {
            int s0 = s_src[wid][k];
            float w0 = s_w[wid][head][k];
            uint4 r0 = ((const uint4*)(hbase + (size_t)s0 * HO))[lane];
            s += w0;
            const half2* h0 = (const half2*)&r0;
            #pragma unroll
            for (int j = 0; j < 4; j++) {
                float2 f0 = __half22float2(h0[j]);
                a[2 * j]     += w0 * f0.x;
                a[2 * j + 1] += w0 * f0.y;
            }
        }
        __syncwarp();
    }

    float r = (s > 0.f) ? 1.0f / s : 0.f;
    const float* bp = bias + p * HO + lane * 8;
    float4 b0 = *(const float4*)bp;
    float4 b1 = *(const float4*)(bp + 4);
    float bb[8] = {b0.x, b0.y, b0.z, b0.w, b1.x, b1.y, b1.z, b1.w};
    half2 zv[4];
    #pragma unroll
    for (int j = 0; j < 4; j++) {
        float za = elu_f(a[2 * j] * r + bb[2 * j]);
        float zb = elu_f(a[2 * j + 1] * r + bb[2 * j + 1]);
        zv[j] = __floats2half2_rn(za, zb);
    }
    *(uint4*)(g_z + (size_t)nd * HO + lane * 8) = *(uint4*)zv;
}

// ===== semantic: wsum[p] += sum_n tanh(z @ W1 + b1) . w2  (fp16 HMMA) =====
// A = z fp16 [64 x 32] per k-block, stride 20 u32; B = W1T fp16 [128 n x 32 k], stride 20 u32.
constexpr int AH_STR = 20;    // u32 per A row (32 halves + pad)
constexpr int BH_STR = 20;    // u32 per B row

__global__ void __launch_bounds__(256) sem_kernel(const float* __restrict__ b1,
                                                  const float* __restrict__ w2) {
    int p = blockIdx.y;
    int row0 = blockIdx.x * 64;
    __shared__ uint32_t As[64 * AH_STR];
    __shared__ uint32_t Bs[HID * BH_STR];
    __shared__ float bsum;

    int tid = threadIdx.x, lane = tid & 31, warp = tid >> 5;
    int warpm = warp & 1, warpn = warp >> 1;  // 2 x 4
    int gid = lane >> 2, tig = lane & 3;
    const __half* zb = g_z + (size_t)p * NN * HO;
    if (tid == 0) bsum = 0.f;

    float c[2][4][4];
    #pragma unroll
    for (int mt = 0; mt < 2; mt++)
        #pragma unroll
        for (int nt = 0; nt < 4; nt++)
            #pragma unroll
            for (int r = 0; r < 4; r++) c[mt][nt][r] = 0.f;

    for (int kb = 0; kb < 8; kb++) {
        // A tile 64x32 halves: one uint4 (8 halves) per thread
        {
            int r = tid >> 2, c8 = tid & 3;
            int gr = row0 + r;
            uint4 v = make_uint4(0u, 0u, 0u, 0u);
            if (gr < NN) v = *(const uint4*)(zb + (size_t)gr * HO + kb * 32 + c8 * 8);
            *(uint4*)(As + r * AH_STR + c8 * 4) = v;
        }
        // B tile: W1T rows n=0..127, halves k in [kb*32, kb*32+32): 512 uint4, 2/thread
        #pragma unroll
        for (int it = 0; it < 2; it++) {
            int idx = tid + it * 256;
            int n = idx >> 2, c8 = idx & 3;
            uint4 v = *(const uint4*)(g_w1t + (size_t)n * HO + kb * 32 + c8 * 8);
            *(uint4*)(Bs + n * BH_STR + c8 * 4) = v;
        }
        __syncthreads();
        #pragma unroll
        for (int ks = 0; ks < 2; ks++) {
            int k0 = ks * 8;  // u32 offset (16 halves)
            uint32_t a[2][4];
            #pragma unroll
            for (int mt = 0; mt < 2; mt++) {
                int rb = warpm * 32 + mt * 16;
                a[mt][0] = As[(rb + gid) * AH_STR + k0 + tig];
                a[mt][1] = As[(rb + gid + 8) * AH_STR + k0 + tig];
                a[mt][2] = As[(rb + gid) * AH_STR + k0 + tig + 4];
                a[mt][3] = As[(rb + gid + 8) * AH_STR + k0 + tig + 4];
            }
            #pragma unroll
            for (int nt = 0; nt < 4; nt++) {
                int n0 = warpn * 32 + nt * 8;
                uint32_t b0 = Bs[(n0 + gid) * BH_STR + k0 + tig];
                uint32_t b1v = Bs[(n0 + gid) * BH_STR + k0 + tig + 4];
                mma_f16(c[0][nt], a[0], b0, b1v);
                mma_f16(c[1][nt], a[1], b0, b1v);
            }
        }
        __syncthreads();
    }

    float part = 0.f;
    #pragma unroll
    for (int mt = 0; mt < 2; mt++) {
        int rb = row0 + warpm * 32 + mt * 16;
        bool ok0 = (rb + gid) < NN, ok1 = (rb + gid + 8) < NN;
        #pragma unroll
        for (int nt = 0; nt < 4; nt++) {
            int col0 = warpn * 32 + nt * 8 + 2 * tig;
            float b1a = b1[col0], b1b = b1[col0 + 1];
            float w2a = w2[col0], w2b = w2[col0 + 1];
            if (ok0) part += tanh_fast(c[mt][nt][0] + b1a) * w2a +
                             tanh_fast(c[mt][nt][1] + b1b) * w2b;
            if (ok1) part += tanh_fast(c[mt][nt][2] + b1a) * w2a +
                             tanh_fast(c[mt][nt][3] + b1b) * w2b;
        }
    }
    #pragma unroll
    for (int off = 16; off; off >>= 1)
        part += __shfl_xor_sync(0xffffffffu, part, off);
    __syncthreads();
    if (lane == 0) atomicAdd(&bsum, part);
    __syncthreads();
    if (tid == 0) atomicAdd(&g_wsum[p], bsum);
}

__global__ void beta_kernel() {
    if (threadIdx.x == 0) {
        float w0 = g_wsum[0] / NN, w1 = g_wsum[1] / NN, w2v = g_wsum[2] / NN;
        float mx = fmaxf(w0, fmaxf(w1, w2v));
        float e0 = __expf(w0 - mx), e1 = __expf(w1 - mx), e2 = __expf(w2v - mx);
        float s = e0 + e1 + e2;
        g_beta[0] = e0 / s;
        g_beta[1] = e1 / s;
        g_beta[2] = e2 / s;
    }
}

// out = sum_p beta[p] * z_p  (z fp16, output fp32)
__global__ void final_kernel(float* __restrict__ dout) {
    size_t i = (size_t)blockIdx.x * blockDim.x + threadIdx.x;  // uint4 index (8 halves)
    size_t total = (size_t)NN * HO / 8;
    if (i >= total) return;
    float bw[3] = {g_beta[0], g_beta[1], g_beta[2]};
    float r[8];
    #pragma unroll
    for (int j = 0; j < 8; j++) r[j] = 0.f;
    #pragma unroll
    for (int p = 0; p < NP; p++) {
        uint4 v = ((const uint4*)g_z)[(size_t)p * NN * HO / 8 + i];
        const half2* h = (const half2*)&v;
        #pragma unroll
        for (int j = 0; j < 4; j++) {
            float2 f = __half22float2(h[j]);
            r[2 * j]     += bw[p] * f.x;
            r[2 * j + 1] += bw[p] * f.y;
        }
    }
    float4* o = (float4*)dout + i * 2;
    o[0] = make_float4(r[0], r[1], r[2], r[3]);
    o[1] = make_float4(r[4], r[5], r[6], r[7]);
}

// ---------------- launch ----------------
extern "C" void kernel_launch(void* const* d_in, const int* in_sizes, int n_in,
                              void* d_out, int out_size) {
    const float* feat  = (const float*)d_in[0];
    const void*  edges = d_in[1];
    const float* Ws    = (const float*)d_in[2];
    const float* al    = (const float*)d_in[3];
    const float* ar    = (const float*)d_in[4];
    const float* bias  = (const float*)d_in[5];
    const float* W1    = (const float*)d_in[6];
    const float* b1    = (const float*)d_in[7];
    const float* w2    = (const float*)d_in[8];
    float* outp = (float*)d_out;

    detect_kernel<<<1, 32>>>((const int*)edges);
    init_small<<<(NP * NN + 255) / 256, 256>>>();
    w1t_kernel<<<(HID * HO + 255) / 256, 256>>>(W1);

    dim3 gh((NN + 63) / 64, NP);
    gemm_h<<<gh, 256>>>(feat, Ws, al, ar);

    dim3 ge((NE + 255) / 256, NP);
    hist_kernel<<<ge, 256>>>(edges);
    scan_kernel<<<NP, 1024>>>();
    scatter_kernel<<<ge, 256>>>(edges);

    agg_csr<<<dim3((NN + 7) / 8, NP), 256>>>(bias);

    sem_kernel<<<gh, 256>>>(b1, w2);
    beta_kernel<<<1, 32>>>();

    final_kernel<<<(int)(((size_t)NN * HO / 8 + 255) / 256), 256>>>(outp);
}

// round 17
// speedup vs baseline: 3.8226x; 1.0332x over previous
#include <cuda_runtime.h>
#include <cuda_fp16.h>
#include <math.h>
#include <stdint.h>

// Problem constants
constexpr int NN  = 50000;   // nodes
constexpr int DIN = 128;     // input feature dim
constexpr int HO  = 256;     // H*O
constexpr int NH  = 8;       // heads
constexpr int NE  = 400000;  // edges per path
constexpr int NP  = 3;       // metapaths
constexpr int HID = 128;     // semantic hidden

// ---------------- scratch (static device globals; no allocation) ----------------
__device__ __half g_h [(size_t)NP * NN * HO];   // per-path projected features (fp16)
__device__ __half g_z [(size_t)NP * NN * HO];   // per-path z = elu(out+bias) (fp16)
__device__ __half g_featH[(size_t)NN * DIN];    // feat in fp16
__device__ __half g_wt[(size_t)NP * HO * DIN];  // Ws transposed [p][n][k], fp16
__device__ float g_el [NP * NN * NH];
__device__ float g_er [NP * NN * NH];
__device__ int   g_cnt[NP * NN];                // in-degree per dst
__device__ int   g_off[NP * NN];                // CSR exclusive offsets
__device__ int   g_cur[NP * NN];                // scatter cursors
__device__ int   g_csr[(size_t)NP * NE];        // src node per CSR slot
__device__ __half g_wcsr[(size_t)NP * NE * NH]; // per-slot softmax weights (8 heads, fp16)
__device__ __half g_w1t[HID * HO];              // W1 transposed [n][k], fp16
__device__ float g_wsum[NP];
__device__ float g_beta[NP];
__device__ int   g_is64;

// ---------------- helpers ----------------
__device__ __forceinline__ float elu_f(float x) { return x > 0.f ? x : expm1f(x); }

__device__ __forceinline__ float tanh_fast(float x) {
    float y;
    asm("tanh.approx.f32 %0, %1;" : "=f"(y) : "f"(x));
    return y;
}

// D += A(16x16) * B(16x8), fp16 in, f32 accumulate
__device__ __forceinline__ void mma_f16(float* c, const uint32_t* a,
                                        uint32_t b0, uint32_t b1) {
    asm volatile(
        "mma.sync.aligned.m16n8k16.row.col.f32.f16.f16.f32 "
        "{%0,%1,%2,%3}, {%4,%5,%6,%7}, {%8,%9}, {%0,%1,%2,%3};\n"
        : "+f"(c[0]), "+f"(c[1]), "+f"(c[2]), "+f"(c[3])
        : "r"(a[0]), "r"(a[1]), "r"(a[2]), "r"(a[3]), "r"(b0), "r"(b1));
}

// edges may be int64 (jax x64) or int32 (x64 disabled) — uniform device branch
__device__ __forceinline__ int edge_val(const void* edges, size_t idx) {
    if (g_is64) return (int)(((const long long*)edges)[idx]);
    return ((const int*)edges)[idx];
}

// ---------------- kernels ----------------
__global__ void detect_kernel(const int* e32) {
    if (threadIdx.x == 0 && blockIdx.x == 0) {
        int is64 = 1;
        #pragma unroll
        for (int k = 0; k < 16; k++)
            if (e32[2 * k + 1] != 0) is64 = 0;
        g_is64 = is64;
    }
}

// zero counters / cursors / wsum
__global__ void init_small() {
    int i = blockIdx.x * blockDim.x + threadIdx.x;
    if (i < NP * NN) {
        g_cnt[i] = 0;
        g_cur[i] = 0;
    }
    if (i < NP) g_wsum[i] = 0.f;
}

// one-off conversions
__global__ void feat_conv(const float* __restrict__ feat) {
    size_t i = (size_t)blockIdx.x * blockDim.x + threadIdx.x;
    if (i >= (size_t)NN * DIN / 2) return;
    float2 v = ((const float2*)feat)[i];
    ((half2*)g_featH)[i] = __floats2half2_rn(v.x, v.y);
}

__global__ void w_conv(const float* __restrict__ Ws) {
    int i = blockIdx.x * blockDim.x + threadIdx.x;
    if (i >= NP * DIN * HO) return;
    int p = i / (DIN * HO), rem = i % (DIN * HO);
    int k = rem / HO, n = rem % HO;
    g_wt[(size_t)p * HO * DIN + n * DIN + k] = __float2half_rn(Ws[i]);
}

__global__ void w1t_kernel(const float* __restrict__ W1) {
    int i = blockIdx.x * blockDim.x + threadIdx.x;
    if (i >= HID * HO) return;
    int k = i >> 7, n = i & 127;          // coalesced read of W1
    g_w1t[n * HO + k] = __float2half_rn(W1[(size_t)k * HID + n]);
}

// ===== h_p = feat @ W_p  (fp16 HMMA m16n8k16), h stored as fp16 =====
// Block 64 rows x 256 cols, 8 warps 2(m) x 4(n), warp tile 32x64. BK=32 halves.
constexpr int AH_STR = 20;    // u32 per A row (16 u32 data + 4 pad)
constexpr int BH_STR = 20;    // u32 per B row

__global__ void __launch_bounds__(256) gemm_h(const float* __restrict__ al,
                                              const float* __restrict__ ar) {
    int p = blockIdx.y;
    int row0 = blockIdx.x * 64;
    const __half* Wt = g_wt + (size_t)p * HO * DIN;
    __shared__ uint32_t As[64 * AH_STR];
    __shared__ uint32_t Bs[HO * BH_STR];
    __shared__ float al_s[HO], ar_s[HO];

    int tid = threadIdx.x, lane = tid & 31, warp = tid >> 5;
    int warpm = warp & 1, warpn = warp >> 1;  // 2 x 4
    int gid = lane >> 2, tig = lane & 3;

    al_s[tid] = al[p * HO + tid];
    ar_s[tid] = ar[p * HO + tid];

    float c[2][8][4];
    #pragma unroll
    for (int mt = 0; mt < 2; mt++)
        #pragma unroll
        for (int nt = 0; nt < 8; nt++)
            #pragma unroll
            for (int r = 0; r < 4; r++) c[mt][nt][r] = 0.f;

    for (int kb = 0; kb < 4; kb++) {
        // A tile: 64 rows x 32 halves = 256 uint4, one per thread
        {
            int r = tid >> 2, c8 = tid & 3;
            int gr = row0 + r;
            uint4 v = make_uint4(0u, 0u, 0u, 0u);
            if (gr < NN) v = *(const uint4*)(g_featH + (size_t)gr * DIN + kb * 32 + c8 * 8);
            *(uint4*)(As + r * AH_STR + c8 * 4) = v;
        }
        // B tile: 256 n-rows x 32 halves = 1024 uint4, 4 per thread
        #pragma unroll
        for (int it = 0; it < 4; it++) {
            int idx = tid + it * 256;
            int n = idx >> 2, c8 = idx & 3;
            uint4 v = *(const uint4*)(Wt + (size_t)n * DIN + kb * 32 + c8 * 8);
            *(uint4*)(Bs + n * BH_STR + c8 * 4) = v;
        }
        __syncthreads();
        #pragma unroll
        for (int ks = 0; ks < 2; ks++) {
            int k0 = ks * 8;  // u32 offset (16 halves)
            uint32_t a[2][4];
            #pragma unroll
            for (int mt = 0; mt < 2; mt++) {
                int rb = warpm * 32 + mt * 16;
                a[mt][0] = As[(rb + gid) * AH_STR + k0 + tig];
                a[mt][1] = As[(rb + gid + 8) * AH_STR + k0 + tig];
                a[mt][2] = As[(rb + gid) * AH_STR + k0 + tig + 4];
                a[mt][3] = As[(rb + gid + 8) * AH_STR + k0 + tig + 4];
            }
            #pragma unroll
            for (int nt = 0; nt < 8; nt++) {
                int n0 = warpn * 64 + nt * 8;
                uint32_t b0 = Bs[(n0 + gid) * BH_STR + k0 + tig];
                uint32_t b1 = Bs[(n0 + gid) * BH_STR + k0 + tig + 4];
                mma_f16(c[0][nt], a[0], b0, b1);
                mma_f16(c[1][nt], a[1], b0, b1);
            }
        }
        __syncthreads();
    }

    // epilogue: store h (fp16), fused el/er (warp covers heads warpn*2, warpn*2+1)
    int node[2][2];
    #pragma unroll
    for (int mt = 0; mt < 2; mt++) {
        node[mt][0] = row0 + warpm * 32 + mt * 16 + gid;
        node[mt][1] = node[mt][0] + 8;
    }
    float pl[2][2][2], pr[2][2][2];
    #pragma unroll
    for (int mt = 0; mt < 2; mt++)
        #pragma unroll
        for (int rh = 0; rh < 2; rh++)
            #pragma unroll
            for (int hl = 0; hl < 2; hl++) { pl[mt][rh][hl] = 0.f; pr[mt][rh][hl] = 0.f; }

    #pragma unroll
    for (int nt = 0; nt < 8; nt++) {
        int col0 = warpn * 64 + nt * 8 + 2 * tig;
        int hl = nt >> 2;
        float a0l = al_s[col0], a1l = al_s[col0 + 1];
        float a0r = ar_s[col0], a1r = ar_s[col0 + 1];
        #pragma unroll
        for (int mt = 0; mt < 2; mt++) {
            float v0 = c[mt][nt][0], v1 = c[mt][nt][1];
            float v2 = c[mt][nt][2], v3 = c[mt][nt][3];
            pl[mt][0][hl] += v0 * a0l + v1 * a1l;
            pr[mt][0][hl] += v0 * a0r + v1 * a1r;
            pl[mt][1][hl] += v2 * a0l + v3 * a1l;
            pr[mt][1][hl] += v2 * a0r + v3 * a1r;
            if (node[mt][0] < NN)
                *(half2*)(g_h + ((size_t)p * NN + node[mt][0]) * HO + col0) =
                    __floats2half2_rn(v0, v1);
            if (node[mt][1] < NN)
                *(half2*)(g_h + ((size_t)p * NN + node[mt][1]) * HO + col0) =
                    __floats2half2_rn(v2, v3);
        }
    }
    #pragma unroll
    for (int off = 1; off <= 2; off <<= 1)
        #pragma unroll
        for (int mt = 0; mt < 2; mt++)
            #pragma unroll
            for (int rh = 0; rh < 2; rh++)
                #pragma unroll
                for (int hl = 0; hl < 2; hl++) {
                    pl[mt][rh][hl] += __shfl_xor_sync(0xffffffffu, pl[mt][rh][hl], off);
                    pr[mt][rh][hl] += __shfl_xor_sync(0xffffffffu, pr[mt][rh][hl], off);
                }
    if (tig == 0) {
        #pragma unroll
        for (int mt = 0; mt < 2; mt++)
            #pragma unroll
            for (int rh = 0; rh < 2; rh++) {
                int nd = node[mt][rh];
                if (nd < NN) {
                    *(float2*)(g_el + ((size_t)p * NN + nd) * NH + warpn * 2) =
                        make_float2(pl[mt][rh][0], pl[mt][rh][1]);
                    *(float2*)(g_er + ((size_t)p * NN + nd) * NH + warpn * 2) =
                        make_float2(pr[mt][rh][0], pr[mt][rh][1]);
                }
            }
    }
}

// CSR build: histogram of dst
__global__ void hist_kernel(const void* __restrict__ edges) {
    int p = blockIdx.y;
    int e = blockIdx.x * blockDim.x + threadIdx.x;
    if (e >= NE) return;
    int dst = edge_val(edges, (size_t)2 * p * NE + NE + e);
    atomicAdd(&g_cnt[p * NN + dst], 1);
}

// exclusive prefix sum over counts, one block (1024 thr) per path
__global__ void __launch_bounds__(1024) scan_kernel() {
    __shared__ int wsum[32];
    __shared__ int carry;
    int p = blockIdx.x;
    int tid = threadIdx.x, lane = tid & 31, wid = tid >> 5;
    if (tid == 0) carry = 0;
    __syncthreads();
    for (int base = 0; base < NN; base += 1024) {
        int i = base + tid;
        int v = (i < NN) ? g_cnt[p * NN + i] : 0;
        int x = v;
        #pragma unroll
        for (int o = 1; o < 32; o <<= 1) {
            int y = __shfl_up_sync(0xffffffffu, x, o);
            if (lane >= o) x += y;
        }
        if (lane == 31) wsum[wid] = x;
        __syncthreads();
        if (wid == 0) {
            int w = wsum[lane];
            #pragma unroll
            for (int o = 1; o < 32; o <<= 1) {
                int y = __shfl_up_sync(0xffffffffu, w, o);
                if (lane >= o) w += y;
            }
            wsum[lane] = w;
        }
        __syncthreads();
        int warp_off = (wid == 0) ? 0 : wsum[wid - 1];
        if (i < NN) g_off[p * NN + i] = carry + warp_off + x - v;
        int total = wsum[31];
        __syncthreads();
        if (tid == 0) carry += total;
        __syncthreads();
    }
}

// scatter src ids into CSR slots AND compute per-edge softmax weights (8 heads, fp16)
__global__ void scatter_kernel(const void* __restrict__ edges) {
    int p = blockIdx.y;
    int e = blockIdx.x * blockDim.x + threadIdx.x;
    if (e >= NE) return;
    size_t base = (size_t)2 * p * NE;
    int src = edge_val(edges, base + e);
    int dst = edge_val(edges, base + NE + e);
    int nd = p * NN + dst;
    int pos = g_off[nd] + atomicAdd(&g_cur[nd], 1);
    size_t slot = (size_t)p * NE + pos;
    g_csr[slot] = src;

    const float* el = g_el + ((size_t)p * NN + src) * NH;
    const float* er = g_er + (size_t)nd * NH;
    float4 e0 = *(const float4*)el;
    float4 e1 = *(const float4*)(el + 4);
    float4 r0 = *(const float4*)er;
    float4 r1 = *(const float4*)(er + 4);
    float xv[8] = {e0.x + r0.x, e0.y + r0.y, e0.z + r0.z, e0.w + r0.w,
                   e1.x + r1.x, e1.y + r1.y, e1.z + r1.z, e1.w + r1.w};
    half2 wv[4];
    #pragma unroll
    for (int j = 0; j < 4; j++) {
        float xa = xv[2 * j],     wa;
        float xb = xv[2 * j + 1], wb;
        xa = xa > 0.f ? xa : 0.2f * xa;
        xb = xb > 0.f ? xb : 0.2f * xb;
        wa = __expf(fminf(xa, 10.f));
        wb = __expf(fminf(xb, 10.f));
        wv[j] = __floats2half2_rn(wa, wb);
    }
    *(uint4*)(g_wcsr + slot * NH) = *(uint4*)wv;
}

// ===== CSR aggregation: one WARP per dst; w precomputed (CSR-ordered fp16) =====
// lane covers cols lane*8 .. lane*8+7 (head = lane>>2): one uint4 (8 halves) per edge.
// Gather loop unrolled by 4 for MLP. Epilogue stores z = elu(out + bias) as fp16.
__global__ void __launch_bounds__(256) agg_csr(const float* __restrict__ bias) {
    int p = blockIdx.y;
    int wid = threadIdx.x >> 5, lane = threadIdx.x & 31;
    int dst = blockIdx.x * 8 + wid;
    if (dst >= NN) return;
    __shared__ float s_w[8][NH][33];
    __shared__ int   s_src[8][32];

    int nd = p * NN + dst;
    int beg = g_off[nd], deg = g_cnt[nd];
    int head = lane >> 2;

    float a[8];
    #pragma unroll
    for (int j = 0; j < 8; j++) a[j] = 0.f;
    float s = 0.f;
    const int* csr = g_csr + (size_t)p * NE + beg;
    const uint4* wcsr = (const uint4*)(g_wcsr + ((size_t)p * NE + beg) * NH);
    const __half* hbase = g_h + (size_t)p * NN * HO;

    for (int c0 = 0; c0 < deg; c0 += 32) {
        int csz = min(32, deg - c0);
        if (lane < csz) {
            s_src[wid][lane] = csr[c0 + lane];
            uint4 wv = wcsr[c0 + lane];
            const half2* wh = (const half2*)&wv;
            #pragma unroll
            for (int j = 0; j < 4; j++) {
                float2 f = __half22float2(wh[j]);
                s_w[wid][2 * j][lane]     = f.x;
                s_w[wid][2 * j + 1][lane] = f.y;
            }
        }
        __syncwarp();
        int k = 0;
        for (; k + 4 <= csz; k += 4) {
            int s0 = s_src[wid][k],     s1 = s_src[wid][k + 1];
            int s2 = s_src[wid][k + 2], s3 = s_src[wid][k + 3];
            float w0 = s_w[wid][head][k],     w1 = s_w[wid][head][k + 1];
            float w2 = s_w[wid][head][k + 2], w3 = s_w[wid][head][k + 3];
            uint4 r0 = ((const uint4*)(hbase + (size_t)s0 * HO))[lane];
            uint4 r1 = ((const uint4*)(hbase + (size_t)s1 * HO))[lane];
            uint4 r2 = ((const uint4*)(hbase + (size_t)s2 * HO))[lane];
            uint4 r3 = ((const uint4*)(hbase + (size_t)s3 * HO))[lane];
            s += (w0 + w1) + (w2 + w3);
            const half2* h0 = (const half2*)&r0;
            const half2* h1 = (const half2*)&r1;
            const half2* h2 = (const half2*)&r2;
            const half2* h3 = (const half2*)&r3;
            #pragma unroll
            for (int j = 0; j < 4; j++) {
                float2 f0 = __half22float2(h0[j]);
                float2 f1 = __half22float2(h1[j]);
                float2 f2 = __half22float2(h2[j]);
                float2 f3 = __half22float2(h3[j]);
                a[2 * j]     += (w0 * f0.x + w1 * f1.x) + (w2 * f2.x + w3 * f3.x);
                a[2 * j + 1] += (w0 * f0.y + w1 * f1.y) + (w2 * f2.y + w3 * f3.y);
            }
        }
        for (; k < csz; k++) {
            int s0 = s_src[wid][k];
            float w0 = s_w[wid][head][k];
            uint4 r0 = ((const uint4*)(hbase + (size_t)s0 * HO))[lane];
            s += w0;
            const half2* h0 = (const half2*)&r0;
            #pragma unroll
            for (int j = 0; j < 4; j++) {
                float2 f0 = __half22float2(h0[j]);
                a[2 * j]     += w0 * f0.x;
                a[2 * j + 1] += w0 * f0.y;
            }
        }
        __syncwarp();
    }

    float r = (s > 0.f) ? 1.0f / s : 0.f;
    const float* bp = bias + p * HO + lane * 8;
    float4 b0 = *(const float4*)bp;
    float4 b1 = *(const float4*)(bp + 4);
    float bb[8] = {b0.x, b0.y, b0.z, b0.w, b1.x, b1.y, b1.z, b1.w};
    half2 zv[4];
    #pragma unroll
    for (int j = 0; j < 4; j++) {
        float za = elu_f(a[2 * j] * r + bb[2 * j]);
        float zb = elu_f(a[2 * j + 1] * r + bb[2 * j + 1]);
        zv[j] = __floats2half2_rn(za, zb);
    }
    *(uint4*)(g_z + (size_t)nd * HO + lane * 8) = *(uint4*)zv;
}

// ===== semantic: wsum[p] += sum_n tanh(z @ W1 + b1) . w2  (fp16 HMMA) =====
__global__ void __launch_bounds__(256) sem_kernel(const float* __restrict__ b1,
                                                  const float* __restrict__ w2) {
    int p = blockIdx.y;
    int row0 = blockIdx.x * 64;
    __shared__ uint32_t As[64 * AH_STR];
    __shared__ uint32_t Bs[HID * BH_STR];
    __shared__ float bsum;

    int tid = threadIdx.x, lane = tid & 31, warp = tid >> 5;
    int warpm = warp & 1, warpn = warp >> 1;  // 2 x 4
    int gid = lane >> 2, tig = lane & 3;
    const __half* zb = g_z + (size_t)p * NN * HO;
    if (tid == 0) bsum = 0.f;

    float c[2][4][4];
    #pragma unroll
    for (int mt = 0; mt < 2; mt++)
        #pragma unroll
        for (int nt = 0; nt < 4; nt++)
            #pragma unroll
            for (int r = 0; r < 4; r++) c[mt][nt][r] = 0.f;

    for (int kb = 0; kb < 8; kb++) {
        // A tile 64x32 halves: one uint4 (8 halves) per thread
        {
            int r = tid >> 2, c8 = tid & 3;
            int gr = row0 + r;
            uint4 v = make_uint4(0u, 0u, 0u, 0u);
            if (gr < NN) v = *(const uint4*)(zb + (size_t)gr * HO + kb * 32 + c8 * 8);
            *(uint4*)(As + r * AH_STR + c8 * 4) = v;
        }
        // B tile: W1T rows n=0..127, halves k in [kb*32, kb*32+32): 512 uint4, 2/thread
        #pragma unroll
        for (int it = 0; it < 2; it++) {
            int idx = tid + it * 256;
            int n = idx >> 2, c8 = idx & 3;
            uint4 v = *(const uint4*)(g_w1t + (size_t)n * HO + kb * 32 + c8 * 8);
            *(uint4*)(Bs + n * BH_STR + c8 * 4) = v;
        }
        __syncthreads();
        #pragma unroll
        for (int ks = 0; ks < 2; ks++) {
            int k0 = ks * 8;  // u32 offset (16 halves)
            uint32_t a[2][4];
            #pragma unroll
            for (int mt = 0; mt < 2; mt++) {
                int rb = warpm * 32 + mt * 16;
                a[mt][0] = As[(rb + gid) * AH_STR + k0 + tig];
                a[mt][1] = As[(rb + gid + 8) * AH_STR + k0 + tig];
                a[mt][2] = As[(rb + gid) * AH_STR + k0 + tig + 4];
                a[mt][3] = As[(rb + gid + 8) * AH_STR + k0 + tig + 4];
            }
            #pragma unroll
            for (int nt = 0; nt < 4; nt++) {
                int n0 = warpn * 32 + nt * 8;
                uint32_t b0 = Bs[(n0 + gid) * BH_STR + k0 + tig];
                uint32_t b1v = Bs[(n0 + gid) * BH_STR + k0 + tig + 4];
                mma_f16(c[0][nt], a[0], b0, b1v);
                mma_f16(c[1][nt], a[1], b0, b1v);
            }
        }
        __syncthreads();
    }

    float part = 0.f;
    #pragma unroll
    for (int mt = 0; mt < 2; mt++) {
        int rb = row0 + warpm * 32 + mt * 16;
        bool ok0 = (rb + gid) < NN, ok1 = (rb + gid + 8) < NN;
        #pragma unroll
        for (int nt = 0; nt < 4; nt++) {
            int col0 = warpn * 32 + nt * 8 + 2 * tig;
            float b1a = b1[col0], b1b = b1[col0 + 1];
            float w2a = w2[col0], w2b = w2[col0 + 1];
            if (ok0) part += tanh_fast(c[mt][nt][0] + b1a) * w2a +
                             tanh_fast(c[mt][nt][1] + b1b) * w2b;
            if (ok1) part += tanh_fast(c[mt][nt][2] + b1a) * w2a +
                             tanh_fast(c[mt][nt][3] + b1b) * w2b;
        }
    }
    #pragma unroll
    for (int off = 16; off; off >>= 1)
        part += __shfl_xor_sync(0xffffffffu, part, off);
    __syncthreads();
    if (lane == 0) atomicAdd(&bsum, part);
    __syncthreads();
    if (tid == 0) atomicAdd(&g_wsum[p], bsum);
}

__global__ void beta_kernel() {
    if (threadIdx.x == 0) {
        float w0 = g_wsum[0] / NN, w1 = g_wsum[1] / NN, w2v = g_wsum[2] / NN;
        float mx = fmaxf(w0, fmaxf(w1, w2v));
        float e0 = __expf(w0 - mx), e1 = __expf(w1 - mx), e2 = __expf(w2v - mx);
        float s = e0 + e1 + e2;
        g_beta[0] = e0 / s;
        g_beta[1] = e1 / s;
        g_beta[2] = e2 / s;
    }
}

// out = sum_p beta[p] * z_p  (z fp16, output fp32)
__global__ void final_kernel(float* __restrict__ dout) {
    size_t i = (size_t)blockIdx.x * blockDim.x + threadIdx.x;  // uint4 index (8 halves)
    size_t total = (size_t)NN * HO / 8;
    if (i >= total) return;
    float bw[3] = {g_beta[0], g_beta[1], g_beta[2]};
    float r[8];
    #pragma unroll
    for (int j = 0; j < 8; j++) r[j] = 0.f;
    #pragma unroll
    for (int p = 0; p < NP; p++) {
        uint4 v = ((const uint4*)g_z)[(size_t)p * NN * HO / 8 + i];
        const half2* h = (const half2*)&v;
        #pragma unroll
        for (int j = 0; j < 4; j++) {
            float2 f = __half22float2(h[j]);
            r[2 * j]     += bw[p] * f.x;
            r[2 * j + 1] += bw[p] * f.y;
        }
    }
    float4* o = (float4*)dout + i * 2;
    o[0] = make_float4(r[0], r[1], r[2], r[3]);
    o[1] = make_float4(r[4], r[5], r[6], r[7]);
}

// ---------------- launch ----------------
extern "C" void kernel_launch(void* const* d_in, const int* in_sizes, int n_in,
                              void* d_out, int out_size) {
    const float* feat  = (const float*)d_in[0];
    const void*  edges = d_in[1];
    const float* Ws    = (const float*)d_in[2];
    const float* al    = (const float*)d_in[3];
    const float* ar    = (const float*)d_in[4];
    const float* bias  = (const float*)d_in[5];
    const float* W1    = (const float*)d_in[6];
    const float* b1    = (const float*)d_in[7];
    const float* w2    = (const float*)d_in[8];
    float* outp = (float*)d_out;

    detect_kernel<<<1, 32>>>((const int*)edges);
    init_small<<<(NP * NN + 255) / 256, 256>>>();
    feat_conv<<<(int)(((size_t)NN * DIN / 2 + 255) / 256), 256>>>(feat);
    w_conv<<<(NP * DIN * HO + 255) / 256, 256>>>(Ws);
    w1t_kernel<<<(HID * HO + 255) / 256, 256>>>(W1);

    dim3 gh((NN + 63) / 64, NP);
    gemm_h<<<gh, 256>>>(al, ar);

    dim3 ge((NE + 255) / 256, NP);
    hist_kernel<<<ge, 256>>>(edges);
    scan_kernel<<<NP, 1024>>>();
    scatter_kernel<<<ge, 256>>>(edges);

    agg_csr<<<dim3((NN + 7) / 8, NP), 256>>>(bias);

    sem_kernel<<<gh, 256>>>(b1, w2);
    beta_kernel<<<1, 32>>>();

    final_kernel<<<(int)(((size_t)NN * HO / 8 + 255) / 256), 256>>>(outp);
}